// round 2
// baseline (speedup 1.0000x reference)
#include <cuda_runtime.h>

#define BSZ   2
#define NSEQ  2048
#define DMOD  1024
#define NH    16
#define DHD   64
#define MROWS (BSZ*NSEQ)
#define KT    32

// Device-global scratch (no allocations allowed).
__device__ float g_Q[BSZ*NH*NSEQ*DHD];
__device__ float g_K[BSZ*NH*NSEQ*DHD];
__device__ float g_V[BSZ*NH*NSEQ*DHD];
__device__ float g_Hm[BSZ*NSEQ*DMOD];

// ---------------------------------------------------------------------------
// 128x128x8 fp32 SGEMM, 256 threads, 8x8 per thread (2x2 quadrants of 4x4).
// splitHeads epilogue writes C into (b, h, n, dh) layout; alpha folds scaling.
// M, N, K assumed multiples of 128/128/8 (true here: 4096 x 1024 x 1024).
// ---------------------------------------------------------------------------
__global__ __launch_bounds__(256)
void sgemm_kernel(const float* __restrict__ A, const float* __restrict__ B,
                  float* __restrict__ C, int M, int N, int K,
                  int splitHeads, float alpha)
{
    __shared__ float As[8*128];   // [k][m] transposed
    __shared__ float Bs[8*128];   // [k][n]
    const int tid = threadIdx.x;
    const int tx = tid & 15;
    const int ty = tid >> 4;
    const int m0 = blockIdx.y * 128;
    const int n0 = blockIdx.x * 128;

    const int arow = tid >> 1;          // 0..127
    const int acol = (tid & 1) << 2;    // 0 or 4
    const int brow = tid >> 5;          // 0..7
    const int bcol = (tid & 31) << 2;   // 0..124

    const float* Aptr = A + (size_t)(m0 + arow) * K + acol;
    const float* Bptr = B + (size_t)brow * N + n0 + bcol;

    float acc[2][2][4][4];
    #pragma unroll
    for (int u = 0; u < 2; u++)
      #pragma unroll
      for (int v = 0; v < 2; v++)
        #pragma unroll
        for (int i = 0; i < 4; i++)
          #pragma unroll
          for (int j = 0; j < 4; j++) acc[u][v][i][j] = 0.f;

    for (int k0 = 0; k0 < K; k0 += 8) {
        float4 a4 = *(const float4*)(Aptr + k0);
        float4 b4 = *(const float4*)(Bptr + (size_t)k0 * N);
        __syncthreads();
        As[(acol+0)*128 + arow] = a4.x;
        As[(acol+1)*128 + arow] = a4.y;
        As[(acol+2)*128 + arow] = a4.z;
        As[(acol+3)*128 + arow] = a4.w;
        *(float4*)(&Bs[brow*128 + bcol]) = b4;
        __syncthreads();
        #pragma unroll
        for (int k = 0; k < 8; k++) {
            float4 ra0 = *(const float4*)(&As[k*128 + ty*4]);
            float4 ra1 = *(const float4*)(&As[k*128 + ty*4 + 64]);
            float4 rb0 = *(const float4*)(&Bs[k*128 + tx*4]);
            float4 rb1 = *(const float4*)(&Bs[k*128 + tx*4 + 64]);
            float ra[2][4] = {{ra0.x,ra0.y,ra0.z,ra0.w},{ra1.x,ra1.y,ra1.z,ra1.w}};
            float rb[2][4] = {{rb0.x,rb0.y,rb0.z,rb0.w},{rb1.x,rb1.y,rb1.z,rb1.w}};
            #pragma unroll
            for (int u = 0; u < 2; u++)
              #pragma unroll
              for (int i = 0; i < 4; i++)
                #pragma unroll
                for (int v = 0; v < 2; v++)
                  #pragma unroll
                  for (int j = 0; j < 4; j++)
                    acc[u][v][i][j] = fmaf(ra[u][i], rb[v][j], acc[u][v][i][j]);
        }
    }

    #pragma unroll
    for (int u = 0; u < 2; u++) {
      #pragma unroll
      for (int i = 0; i < 4; i++) {
        const int m = m0 + ty*4 + u*64 + i;
        #pragma unroll
        for (int v = 0; v < 2; v++) {
            const int n = n0 + tx*4 + v*64;
            float4 r;
            r.x = acc[u][v][i][0]*alpha; r.y = acc[u][v][i][1]*alpha;
            r.z = acc[u][v][i][2]*alpha; r.w = acc[u][v][i][3]*alpha;
            if (splitHeads) {
                const int bb = m >> 11;          // m / NSEQ
                const int nn = m & (NSEQ-1);
                const int hh = n >> 6;           // n / DHD
                const int dh = n & 63;
                *(float4*)(&C[(((size_t)(bb*NH + hh))*NSEQ + nn)*DHD + dh]) = r;
            } else {
                *(float4*)(&C[(size_t)m*N + n]) = r;
            }
        }
      }
    }
}

// ---------------------------------------------------------------------------
// Fused masked flash attention.
// Grid: (NSEQ/64 query tiles, B*H). 256 threads: tx = key/col dim, ty = query.
// Q,K in smem transposed [d][x]; V natural [k][d]; P transposed [k][q] str 68.
// Output written head-merged to Hm (b, n, h*dh).
// ---------------------------------------------------------------------------
__global__ __launch_bounds__(256)
void attn_kernel(const float* __restrict__ Qb, const float* __restrict__ Kb,
                 const float* __restrict__ Vb, const int* __restrict__ vlen,
                 float* __restrict__ Hm)
{
    __shared__ float Qt[64*64];    // [d][q]
    __shared__ float Kt[64*KT];    // [d][k]
    __shared__ float Vs[KT*64];    // [k][d]
    __shared__ float Pt[KT*68];    // [k][q], stride 68

    const int tid = threadIdx.x;
    const int tx = tid & 15;
    const int ty = tid >> 4;
    const int qt = blockIdx.x;
    const int bh = blockIdx.y;
    const int vl = vlen[bh];
    const int ntiles = (vl + KT - 1) / KT;

    // Load Q tile (64 q x 64 d) transposed into Qt[d][q].
    {
        const float* Qg = Qb + ((size_t)bh*NSEQ + (size_t)qt*64)*DHD;
        const int q  = tid & 63;
        const int db = (tid >> 6) * 16;
        #pragma unroll
        for (int it = 0; it < 4; it++) {
            float4 v = *(const float4*)(Qg + q*64 + db + it*4);
            Qt[(db+it*4+0)*64 + q] = v.x;
            Qt[(db+it*4+1)*64 + q] = v.y;
            Qt[(db+it*4+2)*64 + q] = v.z;
            Qt[(db+it*4+3)*64 + q] = v.w;
        }
    }

    float acc[4][4];
    float m_i[4], l_i[4];
    #pragma unroll
    for (int i = 0; i < 4; i++) {
        m_i[i] = -1e30f; l_i[i] = 0.f;
        #pragma unroll
        for (int j = 0; j < 4; j++) acc[i][j] = 0.f;
    }

    const float* Kg = Kb + (size_t)bh*NSEQ*DHD;
    const float* Vg = Vb + (size_t)bh*NSEQ*DHD;

    for (int kt = 0; kt < ntiles; kt++) {
        __syncthreads();  // protect Kt/Vs/Pt from previous iteration readers
        // Load K tile transposed [d][k]: thread handles k=tid&31, d-group tid>>5.
        {
            const int kk = tid & 31;
            const int dg = (tid >> 5) * 8;
            const float* Kr = Kg + (size_t)(kt*KT + kk)*DHD + dg;
            float4 v0 = *(const float4*)(Kr);
            float4 v1 = *(const float4*)(Kr + 4);
            Kt[(dg+0)*KT + kk] = v0.x; Kt[(dg+1)*KT + kk] = v0.y;
            Kt[(dg+2)*KT + kk] = v0.z; Kt[(dg+3)*KT + kk] = v0.w;
            Kt[(dg+4)*KT + kk] = v1.x; Kt[(dg+5)*KT + kk] = v1.y;
            Kt[(dg+6)*KT + kk] = v1.z; Kt[(dg+7)*KT + kk] = v1.w;
        }
        // Load V tile natural [k][d], coalesced float4.
        {
            const float4* Vg4 = (const float4*)(Vg + (size_t)kt*KT*DHD);
            float4* Vs4 = (float4*)Vs;
            Vs4[tid]       = Vg4[tid];
            Vs4[tid + 256] = Vg4[tid + 256];
        }
        __syncthreads();

        // S = Q.K^T for this tile: each thread 4 q x 2 k.
        float s[4][2];
        #pragma unroll
        for (int i = 0; i < 4; i++) { s[i][0] = 0.f; s[i][1] = 0.f; }
        #pragma unroll 8
        for (int d = 0; d < 64; d++) {
            float4 qv = *(const float4*)(&Qt[d*64 + ty*4]);
            float2 kv = *(const float2*)(&Kt[d*KT + tx*2]);
            float qa[4] = {qv.x, qv.y, qv.z, qv.w};
            #pragma unroll
            for (int i = 0; i < 4; i++) {
                s[i][0] = fmaf(qa[i], kv.x, s[i][0]);
                s[i][1] = fmaf(qa[i], kv.y, s[i][1]);
            }
        }
        // Mask keys >= valid_len.
        const int kbase = kt*KT + tx*2;
        if (kbase   >= vl) { s[0][0]=s[1][0]=s[2][0]=s[3][0] = -1e30f; }
        if (kbase+1 >= vl) { s[0][1]=s[1][1]=s[2][1]=s[3][1] = -1e30f; }

        // Online softmax update per q row (reduce across 16 tx lanes).
        #pragma unroll
        for (int i = 0; i < 4; i++) {
            float tm = fmaxf(s[i][0], s[i][1]);
            #pragma unroll
            for (int off = 8; off >= 1; off >>= 1)
                tm = fmaxf(tm, __shfl_xor_sync(0xffffffffu, tm, off, 16));
            float m_new = fmaxf(m_i[i], tm);
            float scale = __expf(m_i[i] - m_new);
            float p0 = __expf(s[i][0] - m_new);
            float p1 = __expf(s[i][1] - m_new);
            float rs = p0 + p1;
            #pragma unroll
            for (int off = 8; off >= 1; off >>= 1)
                rs += __shfl_xor_sync(0xffffffffu, rs, off, 16);
            l_i[i] = l_i[i]*scale + rs;
            m_i[i] = m_new;
            #pragma unroll
            for (int j = 0; j < 4; j++) acc[i][j] *= scale;
            Pt[(tx*2+0)*68 + ty*4 + i] = p0;
            Pt[(tx*2+1)*68 + ty*4 + i] = p1;
        }
        __syncthreads();

        // O += P.V : thread owns q=ty*4+i, d=tx*4+j.
        #pragma unroll 4
        for (int k = 0; k < KT; k++) {
            float4 pv = *(const float4*)(&Pt[k*68 + ty*4]);
            float4 vv = *(const float4*)(&Vs[k*64 + tx*4]);
            float pa[4] = {pv.x, pv.y, pv.z, pv.w};
            float va[4] = {vv.x, vv.y, vv.z, vv.w};
            #pragma unroll
            for (int i = 0; i < 4; i++)
                #pragma unroll
                for (int j = 0; j < 4; j++)
                    acc[i][j] = fmaf(pa[i], va[j], acc[i][j]);
        }
    }

    // Epilogue: normalize and write head-merged (b, n, h*64 + d).
    const int bb = bh >> 4;
    const int hh = bh & 15;
    #pragma unroll
    for (int i = 0; i < 4; i++) {
        float inv = 1.0f / l_i[i];
        const int n = qt*64 + ty*4 + i;
        float4 r;
        r.x = acc[i][0]*inv; r.y = acc[i][1]*inv;
        r.z = acc[i][2]*inv; r.w = acc[i][3]*inv;
        *(float4*)(&Hm[((size_t)(bb*NSEQ + n))*DMOD + hh*64 + tx*4]) = r;
    }
}

extern "C" void kernel_launch(void* const* d_in, const int* in_sizes, int n_in,
                              void* d_out, int out_size) {
    const float* queries = (const float*)d_in[0];
    const float* keys    = (const float*)d_in[1];
    const float* values  = (const float*)d_in[2];
    const int*   vlen    = (const int*)  d_in[3];
    const float* Wq      = (const float*)d_in[4];
    const float* Wk      = (const float*)d_in[5];
    const float* Wv      = (const float*)d_in[6];
    const float* Wo      = (const float*)d_in[7];
    float* out = (float*)d_out;

    float *pQ, *pK, *pV, *pH;
    cudaGetSymbolAddress((void**)&pQ, g_Q);
    cudaGetSymbolAddress((void**)&pK, g_K);
    cudaGetSymbolAddress((void**)&pV, g_V);
    cudaGetSymbolAddress((void**)&pH, g_Hm);

    dim3 gg(DMOD/128, MROWS/128);   // (8, 32)
    sgemm_kernel<<<gg, 256>>>(queries, Wq, pQ, MROWS, DMOD, DMOD, 1, 0.125f);
    sgemm_kernel<<<gg, 256>>>(keys,    Wk, pK, MROWS, DMOD, DMOD, 1, 1.0f);
    sgemm_kernel<<<gg, 256>>>(values,  Wv, pV, MROWS, DMOD, DMOD, 1, 1.0f);

    attn_kernel<<<dim3(NSEQ/64, BSZ*NH), 256>>>(pQ, pK, pV, vlen, pH);

    sgemm_kernel<<<gg, 256>>>(pH, Wo, out, MROWS, DMOD, DMOD, 0, 1.0f);
}

// round 4
// speedup vs baseline: 1.3553x; 1.3553x over previous
#include <cuda_runtime.h>
#include <cuda_bf16.h>
#include <cstdint>

#define BSZ   2
#define NSEQ  2048
#define DMOD  1024
#define NH    16
#define DHD   64
#define MROWS (BSZ*NSEQ)
#define KT    32

// ---------------- device scratch (no allocations allowed) ----------------
__device__ float g_Q[BSZ*NH*NSEQ*DHD];
__device__ float g_K[BSZ*NH*NSEQ*DHD];
__device__ float g_V[BSZ*NH*NSEQ*DHD];
__device__ float g_Hm[BSZ*NSEQ*DMOD];
__device__ __nv_bfloat16 g_Ah[MROWS*DMOD];
__device__ __nv_bfloat16 g_Al[MROWS*DMOD];
__device__ __nv_bfloat16 g_Wth[DMOD*DMOD];
__device__ __nv_bfloat16 g_Wtl[DMOD*DMOD];

// ---------------- sm_80-era PTX helpers (compile on base sm_103 target) ----
__device__ __forceinline__ uint32_t smem_to_u32(const void* p) {
    uint32_t a;
    asm("{ .reg .u64 t; cvta.to.shared.u64 t, %1; cvt.u32.u64 %0, t; }" : "=r"(a) : "l"(p));
    return a;
}
__device__ __forceinline__ void cp_async16(uint32_t dst, const void* src) {
    asm volatile("cp.async.cg.shared.global [%0], [%1], 16;" :: "r"(dst), "l"(src));
}
__device__ __forceinline__ void cp_commit() {
    asm volatile("cp.async.commit_group;" ::: "memory");
}
template <int N>
__device__ __forceinline__ void cp_wait() {
    asm volatile("cp.async.wait_group %0;" :: "n"(N) : "memory");
}
__device__ __forceinline__ void ldsm_x4(uint32_t& r0, uint32_t& r1, uint32_t& r2,
                                        uint32_t& r3, uint32_t addr) {
    asm volatile("ldmatrix.sync.aligned.m8n8.x4.shared.b16 {%0,%1,%2,%3}, [%4];"
                 : "=r"(r0), "=r"(r1), "=r"(r2), "=r"(r3) : "r"(addr));
}
__device__ __forceinline__ void mma16816(float* c, uint32_t a0, uint32_t a1,
                                         uint32_t a2, uint32_t a3,
                                         uint32_t b0, uint32_t b1) {
    asm volatile("mma.sync.aligned.m16n8k16.row.col.f32.bf16.bf16.f32 "
                 "{%0,%1,%2,%3}, {%4,%5,%6,%7}, {%8,%9}, {%0,%1,%2,%3};"
                 : "+f"(c[0]), "+f"(c[1]), "+f"(c[2]), "+f"(c[3])
                 : "r"(a0), "r"(a1), "r"(a2), "r"(a3), "r"(b0), "r"(b1));
}

// ---------------- prep kernels ----------------
__global__ __launch_bounds__(256)
void asplit_kernel(const float4* __restrict__ X, uint2* __restrict__ Xh,
                   uint2* __restrict__ Xl, int n4)
{
    int i = blockIdx.x*256 + threadIdx.x;
    if (i >= n4) return;
    float4 v = X[i];
    float a[4] = {v.x, v.y, v.z, v.w};
    uint32_t hb[4], lb[4];
    #pragma unroll
    for (int j = 0; j < 4; j++) {
        __nv_bfloat16 h = __float2bfloat16(a[j]);
        __nv_bfloat16 l = __float2bfloat16(a[j] - __bfloat162float(h));
        hb[j] = (uint32_t)__bfloat16_as_ushort(h);
        lb[j] = (uint32_t)__bfloat16_as_ushort(l);
    }
    uint2 uh, ul;
    uh.x = hb[0] | (hb[1] << 16); uh.y = hb[2] | (hb[3] << 16);
    ul.x = lb[0] | (lb[1] << 16); ul.y = lb[2] | (lb[3] << 16);
    Xh[i] = uh; Xl[i] = ul;
}

// Transpose + split weights: Wt[n][k] = split(W[k][n]).  block (32,8), tile 32x32.
__global__ __launch_bounds__(256)
void wsplit_kernel(const float* __restrict__ W, __nv_bfloat16* __restrict__ Wth,
                   __nv_bfloat16* __restrict__ Wtl)
{
    __shared__ float ts[32][33];
    const int tx = threadIdx.x, ty = threadIdx.y;
    const int gx = blockIdx.x*32, gy = blockIdx.y*32;   // gx: n, gy: k
    #pragma unroll
    for (int i = ty; i < 32; i += 8)
        ts[i][tx] = W[(size_t)(gy+i)*DMOD + gx + tx];
    __syncthreads();
    #pragma unroll
    for (int i = ty; i < 32; i += 8) {
        float v = ts[tx][i];                         // = W[gy+tx][gx+i]
        __nv_bfloat16 h = __float2bfloat16(v);
        __nv_bfloat16 l = __float2bfloat16(v - __bfloat162float(h));
        Wth[(size_t)(gx+i)*DMOD + gy + tx] = h;
        Wtl[(size_t)(gx+i)*DMOD + gy + tx] = l;
    }
}

// ---------------- mma.sync bf16-split GEMM ----------------
// C[4096,1024] = (Ah+Al)[4096,1024] . (Bh+Bl)^T, B* = Wt[n][k] (K-major).
// CTA 128x128, 8 warps of 64x32. K chunks of 32, cp.async double-buffered.
// Smem rows padded to 80B (40 bf16): conflict-free ldmatrix.
#define KC       32
#define NCHUNK   (DMOD/KC)
#define ROWB     80
#define TILE_B   (128*ROWB)        // 10240 B
#define STAGE_B  (4*TILE_B)        // Ah, Al, Bh, Bl
#define GSMEM_SZ (2*STAGE_B)       // 81920 B

__device__ __forceinline__ void issue_chunk(uint32_t sb, int stage,
    const __nv_bfloat16* __restrict__ Ah, const __nv_bfloat16* __restrict__ Al,
    const __nv_bfloat16* __restrict__ Bh, const __nv_bfloat16* __restrict__ Bl,
    int m0, int n0, int k0, int tid)
{
    const uint32_t so = sb + stage*STAGE_B;
    const __nv_bfloat16* srcs[4] = {Ah + (size_t)m0*DMOD, Al + (size_t)m0*DMOD,
                                    Bh + (size_t)n0*DMOD, Bl + (size_t)n0*DMOD};
    #pragma unroll
    for (int t = 0; t < 4; t++) {
        #pragma unroll
        for (int i = 0; i < 2; i++) {
            int idx = i*256 + tid;          // 0..511
            int row = idx >> 2;
            int cg  = idx & 3;
            cp_async16(so + t*TILE_B + row*ROWB + cg*16,
                       srcs[t] + (size_t)row*DMOD + k0 + cg*8);
        }
    }
}

__global__ __launch_bounds__(256, 1)
void gemm_mma_kernel(const __nv_bfloat16* __restrict__ Ah, const __nv_bfloat16* __restrict__ Al,
                     const __nv_bfloat16* __restrict__ Bh, const __nv_bfloat16* __restrict__ Bl,
                     float* __restrict__ C, int splitHeads, float alpha)
{
    extern __shared__ char smem[];
    const uint32_t sb = smem_to_u32(smem);
    const int tid = threadIdx.x;
    const int wid = tid >> 5, lane = tid & 31;
    const int n0 = blockIdx.x * 128;
    const int m0 = blockIdx.y * 128;

    const int mw = (wid & 1) * 64;      // warp m offset in tile
    const int nw = (wid >> 1) * 32;     // warp n offset in tile

    // ldmatrix lane address components
    const int a_row = lane & 15;            // m within 16-row tile
    const int a_kh  = lane >> 4;            // k half (0/1)
    const int b_row = ((lane >> 4) << 3) + (lane & 7);  // n within 16
    const int b_kh  = (lane >> 3) & 1;

    float acc[4][4][4];
    #pragma unroll
    for (int mi = 0; mi < 4; mi++)
      #pragma unroll
      for (int ni = 0; ni < 4; ni++)
        #pragma unroll
        for (int r = 0; r < 4; r++) acc[mi][ni][r] = 0.f;

    issue_chunk(sb, 0, Ah, Al, Bh, Bl, m0, n0, 0, tid);
    cp_commit();

    for (int c = 0; c < NCHUNK; c++) {
        if (c + 1 < NCHUNK) {
            issue_chunk(sb, (c+1) & 1, Ah, Al, Bh, Bl, m0, n0, (c+1)*KC, tid);
            cp_commit();
            cp_wait<1>();
        } else {
            cp_wait<0>();
        }
        __syncthreads();

        const uint32_t so = sb + (c & 1)*STAGE_B;
        #pragma unroll
        for (int ks = 0; ks < 2; ks++) {
            const uint32_t koff = (ks*16 + b_kh*8) * 2;
            uint32_t bh[2][4], bl[2][4];
            #pragma unroll
            for (int np = 0; np < 2; np++) {
                uint32_t ba = so + 2*TILE_B + (nw + np*16 + b_row)*ROWB + koff;
                ldsm_x4(bh[np][0], bh[np][1], bh[np][2], bh[np][3], ba);
                ldsm_x4(bl[np][0], bl[np][1], bl[np][2], bl[np][3], ba + TILE_B);
            }
            const uint32_t akoff = (ks*16 + a_kh*8) * 2;
            #pragma unroll
            for (int mi = 0; mi < 4; mi++) {
                uint32_t aa = so + (mw + mi*16 + a_row)*ROWB + akoff;
                uint32_t ah0, ah1, ah2, ah3, al0, al1, al2, al3;
                ldsm_x4(ah0, ah1, ah2, ah3, aa);
                ldsm_x4(al0, al1, al2, al3, aa + TILE_B);
                #pragma unroll
                for (int ni = 0; ni < 4; ni++) {
                    const int np = ni >> 1, hf = (ni & 1) * 2;
                    mma16816(acc[mi][ni], ah0, ah1, ah2, ah3, bh[np][hf], bh[np][hf+1]);
                    mma16816(acc[mi][ni], ah0, ah1, ah2, ah3, bl[np][hf], bl[np][hf+1]);
                    mma16816(acc[mi][ni], al0, al1, al2, al3, bh[np][hf], bh[np][hf+1]);
                }
            }
        }
        __syncthreads();
    }

    // Epilogue: c frag lane mapping: rows lane>>2 (+8), cols (lane&3)*2 (+1).
    const int crow = lane >> 2, ccol = (lane & 3) * 2;
    #pragma unroll
    for (int mi = 0; mi < 4; mi++) {
      #pragma unroll
      for (int h = 0; h < 2; h++) {
        const int m = m0 + mw + mi*16 + crow + h*8;
        #pragma unroll
        for (int ni = 0; ni < 4; ni++) {
            const int n = n0 + nw + ni*8 + ccol;
            float2 v;
            v.x = acc[mi][ni][h*2+0] * alpha;
            v.y = acc[mi][ni][h*2+1] * alpha;
            if (splitHeads) {
                const int bb = m >> 11, nn = m & (NSEQ-1);
                const int hh = n >> 6, dh = n & 63;
                *(float2*)(&C[(((size_t)(bb*NH + hh))*NSEQ + nn)*DHD + dh]) = v;
            } else {
                *(float2*)(&C[(size_t)m*DMOD + n]) = v;
            }
        }
      }
    }
}

// ---------------------------------------------------------------------------
// Fused masked flash attention (unchanged from round 2).
// ---------------------------------------------------------------------------
__global__ __launch_bounds__(256)
void attn_kernel(const float* __restrict__ Qb, const float* __restrict__ Kb,
                 const float* __restrict__ Vb, const int* __restrict__ vlen,
                 float* __restrict__ Hm)
{
    __shared__ float Qt[64*64];    // [d][q]
    __shared__ float Kt[64*KT];    // [d][k]
    __shared__ float Vs[KT*64];    // [k][d]
    __shared__ float Pt[KT*68];    // [k][q], stride 68

    const int tid = threadIdx.x;
    const int tx = tid & 15;
    const int ty = tid >> 4;
    const int qt = blockIdx.x;
    const int bh = blockIdx.y;
    const int vl = vlen[bh];
    const int ntiles = (vl + KT - 1) / KT;

    {
        const float* Qg = Qb + ((size_t)bh*NSEQ + (size_t)qt*64)*DHD;
        const int q  = tid & 63;
        const int db = (tid >> 6) * 16;
        #pragma unroll
        for (int it = 0; it < 4; it++) {
            float4 v = *(const float4*)(Qg + q*64 + db + it*4);
            Qt[(db+it*4+0)*64 + q] = v.x;
            Qt[(db+it*4+1)*64 + q] = v.y;
            Qt[(db+it*4+2)*64 + q] = v.z;
            Qt[(db+it*4+3)*64 + q] = v.w;
        }
    }

    float acc[4][4];
    float m_i[4], l_i[4];
    #pragma unroll
    for (int i = 0; i < 4; i++) {
        m_i[i] = -1e30f; l_i[i] = 0.f;
        #pragma unroll
        for (int j = 0; j < 4; j++) acc[i][j] = 0.f;
    }

    const float* Kg = Kb + (size_t)bh*NSEQ*DHD;
    const float* Vg = Vb + (size_t)bh*NSEQ*DHD;

    for (int kt = 0; kt < ntiles; kt++) {
        __syncthreads();
        {
            const int kk = tid & 31;
            const int dg = (tid >> 5) * 8;
            const float* Kr = Kg + (size_t)(kt*KT + kk)*DHD + dg;
            float4 v0 = *(const float4*)(Kr);
            float4 v1 = *(const float4*)(Kr + 4);
            Kt[(dg+0)*KT + kk] = v0.x; Kt[(dg+1)*KT + kk] = v0.y;
            Kt[(dg+2)*KT + kk] = v0.z; Kt[(dg+3)*KT + kk] = v0.w;
            Kt[(dg+4)*KT + kk] = v1.x; Kt[(dg+5)*KT + kk] = v1.y;
            Kt[(dg+6)*KT + kk] = v1.z; Kt[(dg+7)*KT + kk] = v1.w;
        }
        {
            const float4* Vg4 = (const float4*)(Vg + (size_t)kt*KT*DHD);
            float4* Vs4 = (float4*)Vs;
            Vs4[tid]       = Vg4[tid];
            Vs4[tid + 256] = Vg4[tid + 256];
        }
        __syncthreads();

        float s[4][2];
        #pragma unroll
        for (int i = 0; i < 4; i++) { s[i][0] = 0.f; s[i][1] = 0.f; }
        #pragma unroll 8
        for (int d = 0; d < 64; d++) {
            float4 qv = *(const float4*)(&Qt[d*64 + ty*4]);
            float2 kv = *(const float2*)(&Kt[d*KT + tx*2]);
            float qa[4] = {qv.x, qv.y, qv.z, qv.w};
            #pragma unroll
            for (int i = 0; i < 4; i++) {
                s[i][0] = fmaf(qa[i], kv.x, s[i][0]);
                s[i][1] = fmaf(qa[i], kv.y, s[i][1]);
            }
        }
        const int kbase = kt*KT + tx*2;
        if (kbase   >= vl) { s[0][0]=s[1][0]=s[2][0]=s[3][0] = -1e30f; }
        if (kbase+1 >= vl) { s[0][1]=s[1][1]=s[2][1]=s[3][1] = -1e30f; }

        #pragma unroll
        for (int i = 0; i < 4; i++) {
            float tm = fmaxf(s[i][0], s[i][1]);
            #pragma unroll
            for (int off = 8; off >= 1; off >>= 1)
                tm = fmaxf(tm, __shfl_xor_sync(0xffffffffu, tm, off, 16));
            float m_new = fmaxf(m_i[i], tm);
            float scale = __expf(m_i[i] - m_new);
            float p0 = __expf(s[i][0] - m_new);
            float p1 = __expf(s[i][1] - m_new);
            float rs = p0 + p1;
            #pragma unroll
            for (int off = 8; off >= 1; off >>= 1)
                rs += __shfl_xor_sync(0xffffffffu, rs, off, 16);
            l_i[i] = l_i[i]*scale + rs;
            m_i[i] = m_new;
            #pragma unroll
            for (int j = 0; j < 4; j++) acc[i][j] *= scale;
            Pt[(tx*2+0)*68 + ty*4 + i] = p0;
            Pt[(tx*2+1)*68 + ty*4 + i] = p1;
        }
        __syncthreads();

        #pragma unroll 4
        for (int k = 0; k < KT; k++) {
            float4 pv = *(const float4*)(&Pt[k*68 + ty*4]);
            float4 vv = *(const float4*)(&Vs[k*64 + tx*4]);
            float pa[4] = {pv.x, pv.y, pv.z, pv.w};
            float va[4] = {vv.x, vv.y, vv.z, vv.w};
            #pragma unroll
            for (int i = 0; i < 4; i++)
                #pragma unroll
                for (int j = 0; j < 4; j++)
                    acc[i][j] = fmaf(pa[i], va[j], acc[i][j]);
        }
    }

    const int bb = bh >> 4;
    const int hh = bh & 15;
    #pragma unroll
    for (int i = 0; i < 4; i++) {
        float inv = 1.0f / l_i[i];
        const int n = qt*64 + ty*4 + i;
        float4 r;
        r.x = acc[i][0]*inv; r.y = acc[i][1]*inv;
        r.z = acc[i][2]*inv; r.w = acc[i][3]*inv;
        *(float4*)(&Hm[((size_t)(bb*NSEQ + n))*DMOD + hh*64 + tx*4]) = r;
    }
}

// ---------------------------------------------------------------------------
extern "C" void kernel_launch(void* const* d_in, const int* in_sizes, int n_in,
                              void* d_out, int out_size) {
    const float* queries = (const float*)d_in[0];
    const float* keys    = (const float*)d_in[1];
    const float* values  = (const float*)d_in[2];
    const int*   vlen    = (const int*)  d_in[3];
    const float* Wq      = (const float*)d_in[4];
    const float* Wk      = (const float*)d_in[5];
    const float* Wv      = (const float*)d_in[6];
    const float* Wo      = (const float*)d_in[7];
    float* out = (float*)d_out;

    float *pQ, *pK, *pV, *pH;
    __nv_bfloat16 *pAh, *pAl, *pWth, *pWtl;
    cudaGetSymbolAddress((void**)&pQ,  g_Q);
    cudaGetSymbolAddress((void**)&pK,  g_K);
    cudaGetSymbolAddress((void**)&pV,  g_V);
    cudaGetSymbolAddress((void**)&pH,  g_Hm);
    cudaGetSymbolAddress((void**)&pAh, g_Ah);
    cudaGetSymbolAddress((void**)&pAl, g_Al);
    cudaGetSymbolAddress((void**)&pWth, g_Wth);
    cudaGetSymbolAddress((void**)&pWtl, g_Wtl);

    cudaFuncSetAttribute(gemm_mma_kernel, cudaFuncAttributeMaxDynamicSharedMemorySize, GSMEM_SZ);

    const int n4 = MROWS*DMOD/4;
    dim3 wgrid(DMOD/32, DMOD/32), wblk(32, 8);
    dim3 ggrid(DMOD/128, MROWS/128);   // (8, 32)

    // Q projection
    wsplit_kernel<<<wgrid, wblk>>>(Wq, pWth, pWtl);
    asplit_kernel<<<n4/256, 256>>>((const float4*)queries, (uint2*)pAh, (uint2*)pAl, n4);
    gemm_mma_kernel<<<ggrid, 256, GSMEM_SZ>>>(pAh, pAl, pWth, pWtl, pQ, 1, 0.125f);
    // K projection
    wsplit_kernel<<<wgrid, wblk>>>(Wk, pWth, pWtl);
    asplit_kernel<<<n4/256, 256>>>((const float4*)keys, (uint2*)pAh, (uint2*)pAl, n4);
    gemm_mma_kernel<<<ggrid, 256, GSMEM_SZ>>>(pAh, pAl, pWth, pWtl, pK, 1, 1.0f);
    // V projection
    wsplit_kernel<<<wgrid, wblk>>>(Wv, pWth, pWtl);
    asplit_kernel<<<n4/256, 256>>>((const float4*)values, (uint2*)pAh, (uint2*)pAl, n4);
    gemm_mma_kernel<<<ggrid, 256, GSMEM_SZ>>>(pAh, pAl, pWth, pWtl, pV, 1, 1.0f);

    // Attention
    attn_kernel<<<dim3(NSEQ/64, BSZ*NH), 256>>>(pQ, pK, pV, vlen, pH);

    // Output projection
    wsplit_kernel<<<wgrid, wblk>>>(Wo, pWth, pWtl);
    asplit_kernel<<<n4/256, 256>>>((const float4*)pH, (uint2*)pAh, (uint2*)pAl, n4);
    gemm_mma_kernel<<<ggrid, 256, GSMEM_SZ>>>(pAh, pAl, pWth, pWtl, out, 0, 1.0f);
}

// round 5
// speedup vs baseline: 2.2898x; 1.6896x over previous
#include <cuda_runtime.h>
#include <cuda_bf16.h>
#include <cstdint>

#define BSZ   2
#define NSEQ  2048
#define DMOD  1024
#define NH    16
#define DHD   64
#define MROWS (BSZ*NSEQ)

// ---------------- device scratch (no allocations allowed) ----------------
__device__ __nv_bfloat16 g_Ah[MROWS*DMOD];
__device__ __nv_bfloat16 g_Al[MROWS*DMOD];
__device__ __nv_bfloat16 g_Wth[DMOD*DMOD];
__device__ __nv_bfloat16 g_Wtl[DMOD*DMOD];
__device__ __nv_bfloat16 g_Qh[MROWS*DMOD];   // [bh][n][dh]
__device__ __nv_bfloat16 g_Ql[MROWS*DMOD];
__device__ __nv_bfloat16 g_Kh[MROWS*DMOD];   // [bh][n][dh]
__device__ __nv_bfloat16 g_Kl[MROWS*DMOD];
__device__ __nv_bfloat16 g_Vth[MROWS*DMOD];  // [bh][dh][n]  (transposed)
__device__ __nv_bfloat16 g_Vtl[MROWS*DMOD];

// ---------------- sm_80-era PTX helpers ----------------
__device__ __forceinline__ uint32_t smem_to_u32(const void* p) {
    uint32_t a;
    asm("{ .reg .u64 t; cvta.to.shared.u64 t, %1; cvt.u32.u64 %0, t; }" : "=r"(a) : "l"(p));
    return a;
}
__device__ __forceinline__ void cp_async16(uint32_t dst, const void* src) {
    asm volatile("cp.async.cg.shared.global [%0], [%1], 16;" :: "r"(dst), "l"(src));
}
__device__ __forceinline__ void cp_commit() {
    asm volatile("cp.async.commit_group;" ::: "memory");
}
template <int N>
__device__ __forceinline__ void cp_wait() {
    asm volatile("cp.async.wait_group %0;" :: "n"(N) : "memory");
}
__device__ __forceinline__ void ldsm_x4(uint32_t& r0, uint32_t& r1, uint32_t& r2,
                                        uint32_t& r3, uint32_t addr) {
    asm volatile("ldmatrix.sync.aligned.m8n8.x4.shared.b16 {%0,%1,%2,%3}, [%4];"
                 : "=r"(r0), "=r"(r1), "=r"(r2), "=r"(r3) : "r"(addr));
}
__device__ __forceinline__ void mma16816(float* c, uint32_t a0, uint32_t a1,
                                         uint32_t a2, uint32_t a3,
                                         uint32_t b0, uint32_t b1) {
    asm volatile("mma.sync.aligned.m16n8k16.row.col.f32.bf16.bf16.f32 "
                 "{%0,%1,%2,%3}, {%4,%5,%6,%7}, {%8,%9}, {%0,%1,%2,%3};"
                 : "+f"(c[0]), "+f"(c[1]), "+f"(c[2]), "+f"(c[3])
                 : "r"(a0), "r"(a1), "r"(a2), "r"(a3), "r"(b0), "r"(b1));
}

// exp on the FMA pipe: exp(x) for x <= 0, ~2e-6 rel err, underflows cleanly.
__device__ __forceinline__ float fexp(float x) {
    float t = x * 1.4426950408889634f;
    t = fmaxf(t, -126.0f);
    float n = rintf(t);
    float f = t - n;
    float p = 1.3333558e-3f;
    p = fmaf(p, f, 9.6181291e-3f);
    p = fmaf(p, f, 5.5504109e-2f);
    p = fmaf(p, f, 2.4022651e-1f);
    p = fmaf(p, f, 6.9314718e-1f);
    p = fmaf(p, f, 1.0f);
    int e = (int)n;
    return p * __int_as_float((e + 127) << 23);
}

__device__ __forceinline__ uint32_t pack_bf16x2(float a, float b) {
    uint32_t ha = (uint32_t)__bfloat16_as_ushort(__float2bfloat16(a));
    uint32_t hb = (uint32_t)__bfloat16_as_ushort(__float2bfloat16(b));
    return ha | (hb << 16);
}
__device__ __forceinline__ float bf16_res(float x) {  // x - bf16(x)
    return x - __bfloat162float(__float2bfloat16(x));
}

// ---------------- prep kernels ----------------
__global__ __launch_bounds__(256)
void asplit_kernel(const float4* __restrict__ X, uint2* __restrict__ Xh,
                   uint2* __restrict__ Xl, int n4)
{
    int i = blockIdx.x*256 + threadIdx.x;
    if (i >= n4) return;
    float4 v = X[i];
    float a[4] = {v.x, v.y, v.z, v.w};
    uint32_t hb[4], lb[4];
    #pragma unroll
    for (int j = 0; j < 4; j++) {
        __nv_bfloat16 h = __float2bfloat16(a[j]);
        __nv_bfloat16 l = __float2bfloat16(a[j] - __bfloat162float(h));
        hb[j] = (uint32_t)__bfloat16_as_ushort(h);
        lb[j] = (uint32_t)__bfloat16_as_ushort(l);
    }
    uint2 uh, ul;
    uh.x = hb[0] | (hb[1] << 16); uh.y = hb[2] | (hb[3] << 16);
    ul.x = lb[0] | (lb[1] << 16); ul.y = lb[2] | (lb[3] << 16);
    Xh[i] = uh; Xl[i] = ul;
}

__global__ __launch_bounds__(256)
void wsplit_kernel(const float* __restrict__ W, __nv_bfloat16* __restrict__ Wth,
                   __nv_bfloat16* __restrict__ Wtl)
{
    __shared__ float ts[32][33];
    const int tx = threadIdx.x, ty = threadIdx.y;
    const int gx = blockIdx.x*32, gy = blockIdx.y*32;
    #pragma unroll
    for (int i = ty; i < 32; i += 8)
        ts[i][tx] = W[(size_t)(gy+i)*DMOD + gx + tx];
    __syncthreads();
    #pragma unroll
    for (int i = ty; i < 32; i += 8) {
        float v = ts[tx][i];
        __nv_bfloat16 h = __float2bfloat16(v);
        __nv_bfloat16 l = __float2bfloat16(v - __bfloat162float(h));
        Wth[(size_t)(gx+i)*DMOD + gy + tx] = h;
        Wtl[(size_t)(gx+i)*DMOD + gy + tx] = l;
    }
}

// ---------------- mma.sync bf16-split GEMM ----------------
// Modes: 0 -> fp32 [m][1024]; 1 -> split bf16 head-layout [bh][n][dh];
//        2 -> split bf16 transposed-V [bh][dh][n].
#define KC       32
#define NCHUNK   (DMOD/KC)
#define ROWB     80
#define TILE_B   (128*ROWB)
#define STAGE_B  (4*TILE_B)
#define GSMEM_SZ (2*STAGE_B)

__device__ __forceinline__ void issue_chunk(uint32_t sb, int stage,
    const __nv_bfloat16* __restrict__ Ah, const __nv_bfloat16* __restrict__ Al,
    const __nv_bfloat16* __restrict__ Bh, const __nv_bfloat16* __restrict__ Bl,
    int m0, int n0, int k0, int tid)
{
    const uint32_t so = sb + stage*STAGE_B;
    const __nv_bfloat16* srcs[4] = {Ah + (size_t)m0*DMOD, Al + (size_t)m0*DMOD,
                                    Bh + (size_t)n0*DMOD, Bl + (size_t)n0*DMOD};
    #pragma unroll
    for (int t = 0; t < 4; t++) {
        #pragma unroll
        for (int i = 0; i < 2; i++) {
            int idx = i*256 + tid;
            int row = idx >> 2;
            int cg  = idx & 3;
            cp_async16(so + t*TILE_B + row*ROWB + cg*16,
                       srcs[t] + (size_t)row*DMOD + k0 + cg*8);
        }
    }
}

__global__ __launch_bounds__(256, 1)
void gemm_mma_kernel(const __nv_bfloat16* __restrict__ Ah, const __nv_bfloat16* __restrict__ Al,
                     const __nv_bfloat16* __restrict__ Bh, const __nv_bfloat16* __restrict__ Bl,
                     float* __restrict__ C32,
                     __nv_bfloat16* __restrict__ Ch, __nv_bfloat16* __restrict__ Cl,
                     int mode, float alpha)
{
    extern __shared__ char smem[];
    const uint32_t sb = smem_to_u32(smem);
    const int tid = threadIdx.x;
    const int wid = tid >> 5, lane = tid & 31;
    const int n0 = blockIdx.x * 128;
    const int m0 = blockIdx.y * 128;

    const int mw = (wid & 1) * 64;
    const int nw = (wid >> 1) * 32;

    const int a_row = lane & 15;
    const int a_kh  = lane >> 4;
    const int b_row = ((lane >> 4) << 3) + (lane & 7);
    const int b_kh  = (lane >> 3) & 1;

    float acc[4][4][4];
    #pragma unroll
    for (int mi = 0; mi < 4; mi++)
      #pragma unroll
      for (int ni = 0; ni < 4; ni++)
        #pragma unroll
        for (int r = 0; r < 4; r++) acc[mi][ni][r] = 0.f;

    issue_chunk(sb, 0, Ah, Al, Bh, Bl, m0, n0, 0, tid);
    cp_commit();

    for (int c = 0; c < NCHUNK; c++) {
        if (c + 1 < NCHUNK) {
            issue_chunk(sb, (c+1) & 1, Ah, Al, Bh, Bl, m0, n0, (c+1)*KC, tid);
            cp_commit();
            cp_wait<1>();
        } else {
            cp_wait<0>();
        }
        __syncthreads();

        const uint32_t so = sb + (c & 1)*STAGE_B;
        #pragma unroll
        for (int ks = 0; ks < 2; ks++) {
            const uint32_t koff = (ks*16 + b_kh*8) * 2;
            uint32_t bh[2][4], bl[2][4];
            #pragma unroll
            for (int np = 0; np < 2; np++) {
                uint32_t ba = so + 2*TILE_B + (nw + np*16 + b_row)*ROWB + koff;
                ldsm_x4(bh[np][0], bh[np][1], bh[np][2], bh[np][3], ba);
                ldsm_x4(bl[np][0], bl[np][1], bl[np][2], bl[np][3], ba + TILE_B);
            }
            const uint32_t akoff = (ks*16 + a_kh*8) * 2;
            #pragma unroll
            for (int mi = 0; mi < 4; mi++) {
                uint32_t aa = so + (mw + mi*16 + a_row)*ROWB + akoff;
                uint32_t ah0, ah1, ah2, ah3, al0, al1, al2, al3;
                ldsm_x4(ah0, ah1, ah2, ah3, aa);
                ldsm_x4(al0, al1, al2, al3, aa + TILE_B);
                #pragma unroll
                for (int ni = 0; ni < 4; ni++) {
                    const int np = ni >> 1, hf = (ni & 1) * 2;
                    mma16816(acc[mi][ni], ah0, ah1, ah2, ah3, bh[np][hf], bh[np][hf+1]);
                    mma16816(acc[mi][ni], ah0, ah1, ah2, ah3, bl[np][hf], bl[np][hf+1]);
                    mma16816(acc[mi][ni], al0, al1, al2, al3, bh[np][hf], bh[np][hf+1]);
                }
            }
        }
        __syncthreads();
    }

    const int crow = lane >> 2, ccol = (lane & 3) * 2;
    #pragma unroll
    for (int mi = 0; mi < 4; mi++) {
      #pragma unroll
      for (int h = 0; h < 2; h++) {
        const int m = m0 + mw + mi*16 + crow + h*8;
        const int bb = m >> 11, nn = m & (NSEQ-1);
        #pragma unroll
        for (int ni = 0; ni < 4; ni++) {
            const int n = n0 + nw + ni*8 + ccol;
            float x0 = acc[mi][ni][h*2+0] * alpha;
            float x1 = acc[mi][ni][h*2+1] * alpha;
            if (mode == 0) {
                float2 v; v.x = x0; v.y = x1;
                *(float2*)(&C32[(size_t)m*DMOD + n]) = v;
            } else if (mode == 1) {
                const int hh = n >> 6, dh = n & 63;
                size_t base = (((size_t)(bb*NH + hh))*NSEQ + nn)*DHD + dh;
                *(uint32_t*)(Ch + base) = pack_bf16x2(x0, x1);
                *(uint32_t*)(Cl + base) = pack_bf16x2(bf16_res(x0), bf16_res(x1));
            } else {
                const int hh = n >> 6, dh = n & 63;
                size_t base = (((size_t)(bb*NH + hh))*DHD + dh)*NSEQ + nn;
                Ch[base]        = __float2bfloat16(x0);
                Ch[base + NSEQ] = __float2bfloat16(x1);
                Cl[base]        = __float2bfloat16(bf16_res(x0));
                Cl[base + NSEQ] = __float2bfloat16(bf16_res(x1));
            }
        }
      }
    }
}

// ---------------- tensor-core flash attention ----------------
// Per CTA: 64 q-rows (4 warps x 16), 64-key tiles, double-buffered K/Vt.
#define AKT   64
#define ASTR  144
#define ATILE (64*ASTR)      // 9216
#define SQH   0
#define SQL   (SQH + ATILE)
#define SKH   (SQL + ATILE)          // [2] stages
#define SKL   (SKH + 2*ATILE)
#define SVH   (SKL + 2*ATILE)
#define SVL   (SVH + 2*ATILE)
#define SPH   (SVL + 2*ATILE)
#define SPL   (SPH + ATILE)
#define ASMEM (SPL + ATILE)          // 110592

__device__ __forceinline__ void attn_load_kv(uint32_t sb, int stage,
    const __nv_bfloat16* __restrict__ Kh, const __nv_bfloat16* __restrict__ Kl,
    const __nv_bfloat16* __restrict__ Vh, const __nv_bfloat16* __restrict__ Vl,
    int bh, int k0, int tid)
{
    const __nv_bfloat16* srcs[4] = {
        Kh + ((size_t)bh*NSEQ + k0)*DHD,
        Kl + ((size_t)bh*NSEQ + k0)*DHD,
        Vh + ((size_t)bh*DHD)*NSEQ + k0,
        Vl + ((size_t)bh*DHD)*NSEQ + k0 };
    const uint32_t dsts[4] = { sb + SKH + stage*ATILE, sb + SKL + stage*ATILE,
                               sb + SVH + stage*ATILE, sb + SVL + stage*ATILE };
    const int rstr[4] = {DHD, DHD, NSEQ, NSEQ};
    #pragma unroll
    for (int i = 0; i < 16; i++) {
        const int arr = i >> 2;                 // compile-time per unrolled i
        const int idx = i*128 + tid;
        const int row = (idx >> 3) & 63;
        const int cg  = idx & 7;
        cp_async16(dsts[arr] + row*ASTR + cg*16,
                   srcs[arr] + (size_t)row*rstr[arr] + cg*8);
    }
}

__global__ __launch_bounds__(128)
void attn_mma_kernel(const __nv_bfloat16* __restrict__ Qh, const __nv_bfloat16* __restrict__ Ql,
                     const __nv_bfloat16* __restrict__ Kh, const __nv_bfloat16* __restrict__ Kl,
                     const __nv_bfloat16* __restrict__ Vh, const __nv_bfloat16* __restrict__ Vl,
                     const int* __restrict__ vlen,
                     __nv_bfloat16* __restrict__ Oh, __nv_bfloat16* __restrict__ Ol)
{
    extern __shared__ char smem[];
    const uint32_t sb = smem_to_u32(smem);
    const int tid = threadIdx.x, wid = tid >> 5, lane = tid & 31;
    const int qt = blockIdx.x, bh = blockIdx.y;
    const int vl = vlen[bh];
    const int ntiles = (vl + AKT - 1) / AKT;
    const int wq0 = wid * 16;

    const int crow = lane >> 2, ccol = (lane & 3) * 2;
    const int a_row = lane & 15, a_kh = lane >> 4;
    const int b_row = ((lane >> 4) << 3) + (lane & 7);
    const int b_kh = (lane >> 3) & 1;

    // prologue: Q tiles + KV stage 0 in one cp.async group
    {
        const __nv_bfloat16* qsrc[2] = { Qh + ((size_t)bh*NSEQ + qt*64)*DHD,
                                         Ql + ((size_t)bh*NSEQ + qt*64)*DHD };
        #pragma unroll
        for (int i = 0; i < 8; i++) {
            const int arr = i >> 2;
            const int idx = i*128 + tid;
            const int row = (idx >> 3) & 63;
            const int cg  = idx & 7;
            cp_async16(sb + (arr ? SQL : SQH) + row*ASTR + cg*16,
                       qsrc[arr] + (size_t)row*DHD + cg*8);
        }
        attn_load_kv(sb, 0, Kh, Kl, Vh, Vl, bh, 0, tid);
        cp_commit();
    }

    float o[8][4];
    float m_i[2] = {-1e30f, -1e30f}, l_i[2] = {0.f, 0.f};
    #pragma unroll
    for (int nt = 0; nt < 8; nt++)
        #pragma unroll
        for (int r = 0; r < 4; r++) o[nt][r] = 0.f;

    for (int kt = 0; kt < ntiles; kt++) {
        cp_wait<0>();
        __syncthreads();
        if (kt + 1 < ntiles) {
            attn_load_kv(sb, (kt+1) & 1, Kh, Kl, Vh, Vl, bh, (kt+1)*AKT, tid);
            cp_commit();
        }
        const uint32_t soK = sb + SKH + (kt & 1)*ATILE;   // +2*ATILE -> Kl
        const uint32_t soV = sb + SVH + (kt & 1)*ATILE;   // +2*ATILE -> Vl

        // ---- S = Q . K^T (hi/lo split, fp32 acc) ----
        float s[8][4];
        #pragma unroll
        for (int nt = 0; nt < 8; nt++)
            #pragma unroll
            for (int r = 0; r < 4; r++) s[nt][r] = 0.f;

        #pragma unroll
        for (int ks = 0; ks < 4; ks++) {
            const uint32_t akoff = (ks*16 + a_kh*8) * 2;
            const uint32_t qa = sb + SQH + (wq0 + a_row)*ASTR + akoff;
            uint32_t qh0,qh1,qh2,qh3, ql0,ql1,ql2,ql3;
            ldsm_x4(qh0,qh1,qh2,qh3, qa);
            ldsm_x4(ql0,ql1,ql2,ql3, qa + ATILE);
            const uint32_t koff = (ks*16 + b_kh*8) * 2;
            #pragma unroll
            for (int np = 0; np < 4; np++) {
                const uint32_t ka = soK + (np*16 + b_row)*ASTR + koff;
                uint32_t kfh[4], kfl[4];
                ldsm_x4(kfh[0],kfh[1],kfh[2],kfh[3], ka);
                ldsm_x4(kfl[0],kfl[1],kfl[2],kfl[3], ka + 2*ATILE);
                #pragma unroll
                for (int t = 0; t < 2; t++) {
                    float* sc = s[np*2 + t];
                    mma16816(sc, qh0,qh1,qh2,qh3, kfh[t*2], kfh[t*2+1]);
                    mma16816(sc, qh0,qh1,qh2,qh3, kfl[t*2], kfl[t*2+1]);
                    mma16816(sc, ql0,ql1,ql2,ql3, kfh[t*2], kfh[t*2+1]);
                }
            }
        }

        // ---- masking + online softmax + split-P to smem ----
        const int kb = kt * AKT;
        const bool full = (kb + AKT <= vl);
        #pragma unroll
        for (int h = 0; h < 2; h++) {
            if (!full) {
                #pragma unroll
                for (int nt = 0; nt < 8; nt++) {
                    const int c0 = kb + nt*8 + ccol;
                    if (c0     >= vl) s[nt][h*2]   = -1e30f;
                    if (c0 + 1 >= vl) s[nt][h*2+1] = -1e30f;
                }
            }
            float rmax = -1e30f;
            #pragma unroll
            for (int nt = 0; nt < 8; nt++)
                rmax = fmaxf(rmax, fmaxf(s[nt][h*2], s[nt][h*2+1]));
            rmax = fmaxf(rmax, __shfl_xor_sync(0xffffffffu, rmax, 1));
            rmax = fmaxf(rmax, __shfl_xor_sync(0xffffffffu, rmax, 2));
            const float m_new = fmaxf(m_i[h], rmax);
            const float rsc = fexp(m_i[h] - m_new);
            m_i[h] = m_new;
            float rsum = 0.f;
            const uint32_t prow = (wq0 + crow + h*8)*ASTR + ccol*2;
            #pragma unroll
            for (int nt = 0; nt < 8; nt++) {
                const float p0 = fexp(s[nt][h*2]   - m_new);
                const float p1 = fexp(s[nt][h*2+1] - m_new);
                rsum += p0 + p1;
                *(uint32_t*)(smem + SPH + prow + nt*16) = pack_bf16x2(p0, p1);
                *(uint32_t*)(smem + SPL + prow + nt*16) = pack_bf16x2(bf16_res(p0), bf16_res(p1));
            }
            rsum += __shfl_xor_sync(0xffffffffu, rsum, 1);
            rsum += __shfl_xor_sync(0xffffffffu, rsum, 2);
            l_i[h] = l_i[h]*rsc + rsum;
            #pragma unroll
            for (int nt = 0; nt < 8; nt++) { o[nt][h*2] *= rsc; o[nt][h*2+1] *= rsc; }
        }
        __syncwarp();

        // ---- O += P . V  (Vt in smem: [dh][key]) ----
        #pragma unroll
        for (int ks = 0; ks < 4; ks++) {
            const uint32_t akoff = (ks*16 + a_kh*8) * 2;
            const uint32_t pa = sb + SPH + (wq0 + a_row)*ASTR + akoff;
            uint32_t ph0,ph1,ph2,ph3, pl0,pl1,pl2,pl3;
            ldsm_x4(ph0,ph1,ph2,ph3, pa);
            ldsm_x4(pl0,pl1,pl2,pl3, pa + ATILE);
            const uint32_t koff = (ks*16 + b_kh*8) * 2;
            #pragma unroll
            for (int np = 0; np < 4; np++) {
                const uint32_t va = soV + (np*16 + b_row)*ASTR + koff;
                uint32_t vfh[4], vfl[4];
                ldsm_x4(vfh[0],vfh[1],vfh[2],vfh[3], va);
                ldsm_x4(vfl[0],vfl[1],vfl[2],vfl[3], va + 2*ATILE);
                #pragma unroll
                for (int t = 0; t < 2; t++) {
                    float* oc = o[np*2 + t];
                    mma16816(oc, ph0,ph1,ph2,ph3, vfh[t*2], vfh[t*2+1]);
                    mma16816(oc, ph0,ph1,ph2,ph3, vfl[t*2], vfl[t*2+1]);
                    mma16816(oc, pl0,pl1,pl2,pl3, vfh[t*2], vfh[t*2+1]);
                }
            }
        }
    }

    // ---- epilogue: normalize, split, write as final-GEMM A operand ----
    const int bb = bh >> 4, hh = bh & 15;
    #pragma unroll
    for (int h = 0; h < 2; h++) {
        const float inv = 1.0f / l_i[h];
        const int ntok = qt*64 + wq0 + crow + h*8;
        const size_t base = ((size_t)(bb*NSEQ) + ntok)*DMOD + hh*64 + ccol;
        #pragma unroll
        for (int nt = 0; nt < 8; nt++) {
            const float x0 = o[nt][h*2]   * inv;
            const float x1 = o[nt][h*2+1] * inv;
            *(uint32_t*)(Oh + base + nt*8) = pack_bf16x2(x0, x1);
            *(uint32_t*)(Ol + base + nt*8) = pack_bf16x2(bf16_res(x0), bf16_res(x1));
        }
    }
}

// ---------------------------------------------------------------------------
extern "C" void kernel_launch(void* const* d_in, const int* in_sizes, int n_in,
                              void* d_out, int out_size) {
    const float* queries = (const float*)d_in[0];
    const float* keys    = (const float*)d_in[1];
    const float* values  = (const float*)d_in[2];
    const int*   vlen    = (const int*)  d_in[3];
    const float* Wq      = (const float*)d_in[4];
    const float* Wk      = (const float*)d_in[5];
    const float* Wv      = (const float*)d_in[6];
    const float* Wo      = (const float*)d_in[7];
    float* out = (float*)d_out;

    __nv_bfloat16 *pAh, *pAl, *pWth, *pWtl, *pQh, *pQl, *pKh, *pKl, *pVh, *pVl;
    cudaGetSymbolAddress((void**)&pAh,  g_Ah);
    cudaGetSymbolAddress((void**)&pAl,  g_Al);
    cudaGetSymbolAddress((void**)&pWth, g_Wth);
    cudaGetSymbolAddress((void**)&pWtl, g_Wtl);
    cudaGetSymbolAddress((void**)&pQh,  g_Qh);
    cudaGetSymbolAddress((void**)&pQl,  g_Ql);
    cudaGetSymbolAddress((void**)&pKh,  g_Kh);
    cudaGetSymbolAddress((void**)&pKl,  g_Kl);
    cudaGetSymbolAddress((void**)&pVh,  g_Vth);
    cudaGetSymbolAddress((void**)&pVl,  g_Vtl);

    cudaFuncSetAttribute(gemm_mma_kernel, cudaFuncAttributeMaxDynamicSharedMemorySize, GSMEM_SZ);
    cudaFuncSetAttribute(attn_mma_kernel, cudaFuncAttributeMaxDynamicSharedMemorySize, ASMEM);

    const int n4 = MROWS*DMOD/4;
    dim3 wgrid(DMOD/32, DMOD/32), wblk(32, 8);
    dim3 ggrid(DMOD/128, MROWS/128);

    // Q projection -> split head layout, scale folded
    wsplit_kernel<<<wgrid, wblk>>>(Wq, pWth, pWtl);
    asplit_kernel<<<n4/256, 256>>>((const float4*)queries, (uint2*)pAh, (uint2*)pAl, n4);
    gemm_mma_kernel<<<ggrid, 256, GSMEM_SZ>>>(pAh, pAl, pWth, pWtl, nullptr, pQh, pQl, 1, 0.125f);
    // K projection
    wsplit_kernel<<<wgrid, wblk>>>(Wk, pWth, pWtl);
    asplit_kernel<<<n4/256, 256>>>((const float4*)keys, (uint2*)pAh, (uint2*)pAl, n4);
    gemm_mma_kernel<<<ggrid, 256, GSMEM_SZ>>>(pAh, pAl, pWth, pWtl, nullptr, pKh, pKl, 1, 1.0f);
    // V projection -> transposed split layout
    wsplit_kernel<<<wgrid, wblk>>>(Wv, pWth, pWtl);
    asplit_kernel<<<n4/256, 256>>>((const float4*)values, (uint2*)pAh, (uint2*)pAl, n4);
    gemm_mma_kernel<<<ggrid, 256, GSMEM_SZ>>>(pAh, pAl, pWth, pWtl, nullptr, pVh, pVl, 2, 1.0f);

    // Attention: writes split output directly into g_Ah/g_Al
    attn_mma_kernel<<<dim3(NSEQ/64, BSZ*NH), 128, ASMEM>>>(pQh, pQl, pKh, pKl, pVh, pVl,
                                                           vlen, pAh, pAl);

    // Output projection
    wsplit_kernel<<<wgrid, wblk>>>(Wo, pWth, pWtl);
    gemm_mma_kernel<<<ggrid, 256, GSMEM_SZ>>>(pAh, pAl, pWth, pWtl, out, nullptr, nullptr, 0, 1.0f);
}

// round 6
// speedup vs baseline: 2.4901x; 1.0875x over previous
#include <cuda_runtime.h>
#include <cuda_bf16.h>
#include <cstdint>

#define BSZ   2
#define NSEQ  2048
#define DMOD  1024
#define NH    16
#define DHD   64
#define MROWS (BSZ*NSEQ)
#define DD    (DMOD*DMOD)

// ---------------- device scratch (no allocations allowed) ----------------
__device__ __nv_bfloat16 g_Ah[3*MROWS*DMOD];   // slot z per input; slot0 reused by attn out
__device__ __nv_bfloat16 g_Al[3*MROWS*DMOD];
__device__ __nv_bfloat16 g_Wth[4*DD];          // Wq, Wk, Wv, Wo (transposed, split)
__device__ __nv_bfloat16 g_Wtl[4*DD];
__device__ __nv_bfloat16 g_Qh[MROWS*DMOD];     // [bh][n][dh]
__device__ __nv_bfloat16 g_Ql[MROWS*DMOD];
__device__ __nv_bfloat16 g_Kh[MROWS*DMOD];     // [bh][n][dh]
__device__ __nv_bfloat16 g_Kl[MROWS*DMOD];
__device__ __nv_bfloat16 g_Vth[MROWS*DMOD];    // [bh][dh][n]  (transposed)
__device__ __nv_bfloat16 g_Vtl[MROWS*DMOD];

// ---------------- sm_80-era PTX helpers ----------------
__device__ __forceinline__ uint32_t smem_to_u32(const void* p) {
    uint32_t a;
    asm("{ .reg .u64 t; cvta.to.shared.u64 t, %1; cvt.u32.u64 %0, t; }" : "=r"(a) : "l"(p));
    return a;
}
__device__ __forceinline__ void cp_async16(uint32_t dst, const void* src) {
    asm volatile("cp.async.cg.shared.global [%0], [%1], 16;" :: "r"(dst), "l"(src));
}
__device__ __forceinline__ void cp_commit() {
    asm volatile("cp.async.commit_group;" ::: "memory");
}
template <int N>
__device__ __forceinline__ void cp_wait() {
    asm volatile("cp.async.wait_group %0;" :: "n"(N) : "memory");
}
__device__ __forceinline__ void ldsm_x4(uint32_t& r0, uint32_t& r1, uint32_t& r2,
                                        uint32_t& r3, uint32_t addr) {
    asm volatile("ldmatrix.sync.aligned.m8n8.x4.shared.b16 {%0,%1,%2,%3}, [%4];"
                 : "=r"(r0), "=r"(r1), "=r"(r2), "=r"(r3) : "r"(addr));
}
__device__ __forceinline__ void mma16816(float* c, uint32_t a0, uint32_t a1,
                                         uint32_t a2, uint32_t a3,
                                         uint32_t b0, uint32_t b1) {
    asm volatile("mma.sync.aligned.m16n8k16.row.col.f32.bf16.bf16.f32 "
                 "{%0,%1,%2,%3}, {%4,%5,%6,%7}, {%8,%9}, {%0,%1,%2,%3};"
                 : "+f"(c[0]), "+f"(c[1]), "+f"(c[2]), "+f"(c[3])
                 : "r"(a0), "r"(a1), "r"(a2), "r"(a3), "r"(b0), "r"(b1));
}

// exp on the FMA pipe: exp(x) for x <= 0, ~2e-6 rel err, underflows cleanly.
__device__ __forceinline__ float fexp(float x) {
    float t = x * 1.4426950408889634f;
    t = fmaxf(t, -126.0f);
    float n = rintf(t);
    float f = t - n;
    float p = 1.3333558e-3f;
    p = fmaf(p, f, 9.6181291e-3f);
    p = fmaf(p, f, 5.5504109e-2f);
    p = fmaf(p, f, 2.4022651e-1f);
    p = fmaf(p, f, 6.9314718e-1f);
    p = fmaf(p, f, 1.0f);
    int e = (int)n;
    return p * __int_as_float((e + 127) << 23);
}

__device__ __forceinline__ uint32_t pack_bf16x2(float a, float b) {
    uint32_t ha = (uint32_t)__bfloat16_as_ushort(__float2bfloat16(a));
    uint32_t hb = (uint32_t)__bfloat16_as_ushort(__float2bfloat16(b));
    return ha | (hb << 16);
}
__device__ __forceinline__ float bf16_res(float x) {
    return x - __bfloat162float(__float2bfloat16(x));
}

// ---------------- prep kernels (fused across operands via blockIdx.z) -------
__global__ __launch_bounds__(256)
void asplit_all(const float4* __restrict__ X0, const float4* __restrict__ X1,
                const float4* __restrict__ X2, uint2* __restrict__ Xh,
                uint2* __restrict__ Xl, int n4)
{
    const int z = blockIdx.z;
    const float4* X = (z == 0) ? X0 : ((z == 1) ? X1 : X2);
    int i = blockIdx.x*256 + threadIdx.x;
    if (i >= n4) return;
    float4 v = X[i];
    float a[4] = {v.x, v.y, v.z, v.w};
    uint32_t hb[4], lb[4];
    #pragma unroll
    for (int j = 0; j < 4; j++) {
        __nv_bfloat16 h = __float2bfloat16(a[j]);
        __nv_bfloat16 l = __float2bfloat16(a[j] - __bfloat162float(h));
        hb[j] = (uint32_t)__bfloat16_as_ushort(h);
        lb[j] = (uint32_t)__bfloat16_as_ushort(l);
    }
    uint2 uh, ul;
    uh.x = hb[0] | (hb[1] << 16); uh.y = hb[2] | (hb[3] << 16);
    ul.x = lb[0] | (lb[1] << 16); ul.y = lb[2] | (lb[3] << 16);
    Xh[(size_t)z*n4 + i] = uh; Xl[(size_t)z*n4 + i] = ul;
}

__global__ __launch_bounds__(256)
void wsplit_all(const float* __restrict__ W0, const float* __restrict__ W1,
                const float* __restrict__ W2, const float* __restrict__ W3,
                __nv_bfloat16* __restrict__ Wth, __nv_bfloat16* __restrict__ Wtl)
{
    __shared__ float ts[32][33];
    const int z = blockIdx.z;
    const float* W = (z == 0) ? W0 : ((z == 1) ? W1 : ((z == 2) ? W2 : W3));
    __nv_bfloat16* th = Wth + (size_t)z*DD;
    __nv_bfloat16* tl = Wtl + (size_t)z*DD;
    const int tx = threadIdx.x, ty = threadIdx.y;
    const int gx = blockIdx.x*32, gy = blockIdx.y*32;
    #pragma unroll
    for (int i = ty; i < 32; i += 8)
        ts[i][tx] = W[(size_t)(gy+i)*DMOD + gx + tx];
    __syncthreads();
    #pragma unroll
    for (int i = ty; i < 32; i += 8) {
        float v = ts[tx][i];
        __nv_bfloat16 h = __float2bfloat16(v);
        __nv_bfloat16 l = __float2bfloat16(v - __bfloat162float(h));
        th[(size_t)(gx+i)*DMOD + gy + tx] = h;
        tl[(size_t)(gx+i)*DMOD + gy + tx] = l;
    }
}

// ---------------- mma.sync bf16-split GEMM (batched via blockIdx.z) --------
#define KC       32
#define NCHUNK   (DMOD/KC)
#define ROWB     80
#define TILE_B   (128*ROWB)
#define STAGE_B  (4*TILE_B)
#define GSMEM_SZ (2*STAGE_B)

struct GemmJob {
    const __nv_bfloat16 *Ah, *Al, *Bh, *Bl;
    float* C32;
    __nv_bfloat16 *Ch, *Cl;
    int mode;          // 0: fp32 [m][D]; 1: split head [bh][n][dh]; 2: split Vt [bh][dh][n]
    float alpha;
};
struct GemmBatch { GemmJob j[3]; };

__device__ __forceinline__ void issue_chunk(uint32_t sb, int stage,
    const __nv_bfloat16* __restrict__ Ah, const __nv_bfloat16* __restrict__ Al,
    const __nv_bfloat16* __restrict__ Bh, const __nv_bfloat16* __restrict__ Bl,
    int m0, int n0, int k0, int tid)
{
    const uint32_t so = sb + stage*STAGE_B;
    const __nv_bfloat16* srcs[4] = {Ah + (size_t)m0*DMOD, Al + (size_t)m0*DMOD,
                                    Bh + (size_t)n0*DMOD, Bl + (size_t)n0*DMOD};
    #pragma unroll
    for (int t = 0; t < 4; t++) {
        #pragma unroll
        for (int i = 0; i < 2; i++) {
            int idx = i*256 + tid;
            int row = idx >> 2;
            int cg  = idx & 3;
            cp_async16(so + t*TILE_B + row*ROWB + cg*16,
                       srcs[t] + (size_t)row*DMOD + k0 + cg*8);
        }
    }
}

__global__ __launch_bounds__(256, 1)
void gemm_mma_kernel(GemmBatch P)
{
    extern __shared__ char smem[];
    const uint32_t sb = smem_to_u32(smem);
    const int tid = threadIdx.x;
    const int wid = tid >> 5, lane = tid & 31;
    const int n0 = blockIdx.x * 128;
    const int m0 = blockIdx.y * 128;
    const GemmJob& J = P.j[blockIdx.z];
    const __nv_bfloat16 *Ah = J.Ah, *Al = J.Al, *Bh = J.Bh, *Bl = J.Bl;

    const int mw = (wid & 1) * 64;
    const int nw = (wid >> 1) * 32;

    const int a_row = lane & 15;
    const int a_kh  = lane >> 4;
    const int b_row = ((lane >> 4) << 3) + (lane & 7);
    const int b_kh  = (lane >> 3) & 1;

    float acc[4][4][4];
    #pragma unroll
    for (int mi = 0; mi < 4; mi++)
      #pragma unroll
      for (int ni = 0; ni < 4; ni++)
        #pragma unroll
        for (int r = 0; r < 4; r++) acc[mi][ni][r] = 0.f;

    issue_chunk(sb, 0, Ah, Al, Bh, Bl, m0, n0, 0, tid);
    cp_commit();

    for (int c = 0; c < NCHUNK; c++) {
        if (c + 1 < NCHUNK) {
            issue_chunk(sb, (c+1) & 1, Ah, Al, Bh, Bl, m0, n0, (c+1)*KC, tid);
            cp_commit();
            cp_wait<1>();
        } else {
            cp_wait<0>();
        }
        __syncthreads();

        const uint32_t so = sb + (c & 1)*STAGE_B;
        #pragma unroll
        for (int ks = 0; ks < 2; ks++) {
            const uint32_t koff = (ks*16 + b_kh*8) * 2;
            uint32_t bh[2][4], bl[2][4];
            #pragma unroll
            for (int np = 0; np < 2; np++) {
                uint32_t ba = so + 2*TILE_B + (nw + np*16 + b_row)*ROWB + koff;
                ldsm_x4(bh[np][0], bh[np][1], bh[np][2], bh[np][3], ba);
                ldsm_x4(bl[np][0], bl[np][1], bl[np][2], bl[np][3], ba + TILE_B);
            }
            const uint32_t akoff = (ks*16 + a_kh*8) * 2;
            #pragma unroll
            for (int mi = 0; mi < 4; mi++) {
                uint32_t aa = so + (mw + mi*16 + a_row)*ROWB + akoff;
                uint32_t ah0, ah1, ah2, ah3, al0, al1, al2, al3;
                ldsm_x4(ah0, ah1, ah2, ah3, aa);
                ldsm_x4(al0, al1, al2, al3, aa + TILE_B);
                #pragma unroll
                for (int ni = 0; ni < 4; ni++) {
                    const int np = ni >> 1, hf = (ni & 1) * 2;
                    mma16816(acc[mi][ni], ah0, ah1, ah2, ah3, bh[np][hf], bh[np][hf+1]);
                    mma16816(acc[mi][ni], ah0, ah1, ah2, ah3, bl[np][hf], bl[np][hf+1]);
                    mma16816(acc[mi][ni], al0, al1, al2, al3, bh[np][hf], bh[np][hf+1]);
                }
            }
        }
        __syncthreads();
    }

    const int crow = lane >> 2, ccol = (lane & 3) * 2;
    const int mode = J.mode;
    const float alpha = J.alpha;
    #pragma unroll
    for (int mi = 0; mi < 4; mi++) {
      #pragma unroll
      for (int h = 0; h < 2; h++) {
        const int m = m0 + mw + mi*16 + crow + h*8;
        const int bb = m >> 11, nn = m & (NSEQ-1);
        #pragma unroll
        for (int ni = 0; ni < 4; ni++) {
            const int n = n0 + nw + ni*8 + ccol;
            float x0 = acc[mi][ni][h*2+0] * alpha;
            float x1 = acc[mi][ni][h*2+1] * alpha;
            if (mode == 0) {
                float2 v; v.x = x0; v.y = x1;
                *(float2*)(&J.C32[(size_t)m*DMOD + n]) = v;
            } else if (mode == 1) {
                const int hh = n >> 6, dh = n & 63;
                size_t base = (((size_t)(bb*NH + hh))*NSEQ + nn)*DHD + dh;
                *(uint32_t*)(J.Ch + base) = pack_bf16x2(x0, x1);
                *(uint32_t*)(J.Cl + base) = pack_bf16x2(bf16_res(x0), bf16_res(x1));
            } else {
                const int hh = n >> 6, dh = n & 63;
                size_t base = (((size_t)(bb*NH + hh))*DHD + dh)*NSEQ + nn;
                J.Ch[base]        = __float2bfloat16(x0);
                J.Ch[base + NSEQ] = __float2bfloat16(x1);
                J.Cl[base]        = __float2bfloat16(bf16_res(x0));
                J.Cl[base + NSEQ] = __float2bfloat16(bf16_res(x1));
            }
        }
      }
    }
}

// ---------------- tensor-core flash attention (register-resident P) --------
#define AKT   64
#define ASTR  144
#define ATILE (64*ASTR)              // 9216
#define SQH   0
#define SQL   ATILE
#define SKV   (2*ATILE)              // + stage*4*ATILE + {KH,KL,VH,VL}*ATILE
#define ASMEM (10*ATILE)             // 92160

__device__ __forceinline__ void attn_load_kv(uint32_t sb, int stage,
    const __nv_bfloat16* __restrict__ Kh, const __nv_bfloat16* __restrict__ Kl,
    const __nv_bfloat16* __restrict__ Vh, const __nv_bfloat16* __restrict__ Vl,
    int bh, int k0, int tid)
{
    const __nv_bfloat16* srcs[4] = {
        Kh + ((size_t)bh*NSEQ + k0)*DHD,
        Kl + ((size_t)bh*NSEQ + k0)*DHD,
        Vh + ((size_t)bh*DHD)*NSEQ + k0,
        Vl + ((size_t)bh*DHD)*NSEQ + k0 };
    const int rstr[4] = {DHD, DHD, NSEQ, NSEQ};
    const uint32_t base = sb + SKV + stage*(4*ATILE);
    #pragma unroll
    for (int i = 0; i < 16; i++) {
        const int arr = i >> 2;
        const int idx = i*128 + tid;
        const int row = (idx >> 3) & 63;
        const int cg  = idx & 7;
        cp_async16(base + arr*ATILE + row*ASTR + cg*16,
                   srcs[arr] + (size_t)row*rstr[arr] + cg*8);
    }
}

__global__ __launch_bounds__(128, 2)
void attn_mma_kernel(const __nv_bfloat16* __restrict__ Qh, const __nv_bfloat16* __restrict__ Ql,
                     const __nv_bfloat16* __restrict__ Kh, const __nv_bfloat16* __restrict__ Kl,
                     const __nv_bfloat16* __restrict__ Vh, const __nv_bfloat16* __restrict__ Vl,
                     const int* __restrict__ vlen,
                     __nv_bfloat16* __restrict__ Oh, __nv_bfloat16* __restrict__ Ol)
{
    extern __shared__ char smem[];
    const uint32_t sb = smem_to_u32(smem);
    const int tid = threadIdx.x, wid = tid >> 5, lane = tid & 31;
    const int qt = blockIdx.x, bh = blockIdx.y;
    const int vl = vlen[bh];
    const int ntiles = (vl + AKT - 1) / AKT;
    const int wq0 = wid * 16;

    const int crow = lane >> 2, ccol = (lane & 3) * 2;
    const int a_row = lane & 15, a_kh = lane >> 4;
    const int b_row = ((lane >> 4) << 3) + (lane & 7);
    const int b_kh = (lane >> 3) & 1;

    // prologue: Q tiles + KV stage 0 in one cp.async group
    {
        const __nv_bfloat16* qsrc[2] = { Qh + ((size_t)bh*NSEQ + qt*64)*DHD,
                                         Ql + ((size_t)bh*NSEQ + qt*64)*DHD };
        #pragma unroll
        for (int i = 0; i < 8; i++) {
            const int arr = i >> 2;
            const int idx = i*128 + tid;
            const int row = (idx >> 3) & 63;
            const int cg  = idx & 7;
            cp_async16(sb + (arr ? SQL : SQH) + row*ASTR + cg*16,
                       qsrc[arr] + (size_t)row*DHD + cg*8);
        }
        attn_load_kv(sb, 0, Kh, Kl, Vh, Vl, bh, 0, tid);
        cp_commit();
    }

    float o[8][4];
    float m_i[2] = {-1e30f, -1e30f}, l_i[2] = {0.f, 0.f};
    #pragma unroll
    for (int nt = 0; nt < 8; nt++)
        #pragma unroll
        for (int r = 0; r < 4; r++) o[nt][r] = 0.f;

    uint32_t qfh[4][4], qfl[4][4];   // Q fragments, loop-invariant

    for (int kt = 0; kt < ntiles; kt++) {
        if (kt + 1 < ntiles) {
            attn_load_kv(sb, (kt+1) & 1, Kh, Kl, Vh, Vl, bh, (kt+1)*AKT, tid);
            cp_commit();
            cp_wait<1>();
        } else {
            cp_wait<0>();
        }
        __syncthreads();

        if (kt == 0) {
            #pragma unroll
            for (int ks = 0; ks < 4; ks++) {
                const uint32_t qa = sb + SQH + (wq0 + a_row)*ASTR + (ks*16 + a_kh*8)*2;
                ldsm_x4(qfh[ks][0], qfh[ks][1], qfh[ks][2], qfh[ks][3], qa);
                ldsm_x4(qfl[ks][0], qfl[ks][1], qfl[ks][2], qfl[ks][3], qa + ATILE);
            }
        }

        const uint32_t soK = sb + SKV + (kt & 1)*(4*ATILE);   // KH; +AT=KL, +2AT=VH, +3AT=VL

        // ---- S = Q . K^T (hi/lo split, fp32 acc) ----
        float s[8][4];
        #pragma unroll
        for (int nt = 0; nt < 8; nt++)
            #pragma unroll
            for (int r = 0; r < 4; r++) s[nt][r] = 0.f;

        #pragma unroll
        for (int ks = 0; ks < 4; ks++) {
            const uint32_t koff = (ks*16 + b_kh*8) * 2;
            #pragma unroll
            for (int np = 0; np < 4; np++) {
                const uint32_t ka = soK + (np*16 + b_row)*ASTR + koff;
                uint32_t kfh[4], kfl[4];
                ldsm_x4(kfh[0], kfh[1], kfh[2], kfh[3], ka);
                ldsm_x4(kfl[0], kfl[1], kfl[2], kfl[3], ka + ATILE);
                #pragma unroll
                for (int t = 0; t < 2; t++) {
                    float* sc = s[np*2 + t];
                    mma16816(sc, qfh[ks][0], qfh[ks][1], qfh[ks][2], qfh[ks][3], kfh[t*2], kfh[t*2+1]);
                    mma16816(sc, qfh[ks][0], qfh[ks][1], qfh[ks][2], qfh[ks][3], kfl[t*2], kfl[t*2+1]);
                    mma16816(sc, qfl[ks][0], qfl[ks][1], qfl[ks][2], qfl[ks][3], kfh[t*2], kfh[t*2+1]);
                }
            }
        }

        // ---- masking + online softmax (p stays in s[][] as fp32) ----
        const int kb = kt * AKT;
        const bool full = (kb + AKT <= vl);
        #pragma unroll
        for (int h = 0; h < 2; h++) {
            if (!full) {
                #pragma unroll
                for (int nt = 0; nt < 8; nt++) {
                    const int c0 = kb + nt*8 + ccol;
                    if (c0     >= vl) s[nt][h*2]   = -1e30f;
                    if (c0 + 1 >= vl) s[nt][h*2+1] = -1e30f;
                }
            }
            float rmax = -1e30f;
            #pragma unroll
            for (int nt = 0; nt < 8; nt++)
                rmax = fmaxf(rmax, fmaxf(s[nt][h*2], s[nt][h*2+1]));
            rmax = fmaxf(rmax, __shfl_xor_sync(0xffffffffu, rmax, 1));
            rmax = fmaxf(rmax, __shfl_xor_sync(0xffffffffu, rmax, 2));
            const float m_new = fmaxf(m_i[h], rmax);
            const float rsc = fexp(m_i[h] - m_new);
            m_i[h] = m_new;
            float rsum = 0.f;
            #pragma unroll
            for (int nt = 0; nt < 8; nt++) {
                const float p0 = fexp(s[nt][h*2]   - m_new);
                const float p1 = fexp(s[nt][h*2+1] - m_new);
                s[nt][h*2]   = p0;
                s[nt][h*2+1] = p1;
                rsum += p0 + p1;
            }
            rsum += __shfl_xor_sync(0xffffffffu, rsum, 1);
            rsum += __shfl_xor_sync(0xffffffffu, rsum, 2);
            l_i[h] = l_i[h]*rsc + rsum;
            #pragma unroll
            for (int nt = 0; nt < 8; nt++) { o[nt][h*2] *= rsc; o[nt][h*2+1] *= rsc; }
        }

        // ---- O += P . V : P fragments built in registers from S C-fragments ----
        #pragma unroll
        for (int ks = 0; ks < 4; ks++) {
            const int t0 = 2*ks, t1 = 2*ks + 1;
            const uint32_t ph0 = pack_bf16x2(s[t0][0], s[t0][1]);
            const uint32_t ph1 = pack_bf16x2(s[t0][2], s[t0][3]);
            const uint32_t ph2 = pack_bf16x2(s[t1][0], s[t1][1]);
            const uint32_t ph3 = pack_bf16x2(s[t1][2], s[t1][3]);
            const uint32_t pl0 = pack_bf16x2(bf16_res(s[t0][0]), bf16_res(s[t0][1]));
            const uint32_t pl1 = pack_bf16x2(bf16_res(s[t0][2]), bf16_res(s[t0][3]));
            const uint32_t pl2 = pack_bf16x2(bf16_res(s[t1][0]), bf16_res(s[t1][1]));
            const uint32_t pl3 = pack_bf16x2(bf16_res(s[t1][2]), bf16_res(s[t1][3]));
            const uint32_t koff = (ks*16 + b_kh*8) * 2;
            #pragma unroll
            for (int np = 0; np < 4; np++) {
                const uint32_t va = soK + 2*ATILE + (np*16 + b_row)*ASTR + koff;
                uint32_t vfh[4], vfl[4];
                ldsm_x4(vfh[0], vfh[1], vfh[2], vfh[3], va);
                ldsm_x4(vfl[0], vfl[1], vfl[2], vfl[3], va + ATILE);
                #pragma unroll
                for (int t = 0; t < 2; t++) {
                    float* oc = o[np*2 + t];
                    mma16816(oc, ph0, ph1, ph2, ph3, vfh[t*2], vfh[t*2+1]);
                    mma16816(oc, ph0, ph1, ph2, ph3, vfl[t*2], vfl[t*2+1]);
                    mma16816(oc, pl0, pl1, pl2, pl3, vfh[t*2], vfh[t*2+1]);
                }
            }
        }
        __syncthreads();   // stage (kt&1) fully consumed before it is refilled
    }

    // ---- epilogue: normalize, split, write as final-GEMM A operand ----
    const int bb = bh >> 4, hh = bh & 15;
    #pragma unroll
    for (int h = 0; h < 2; h++) {
        const float inv = 1.0f / l_i[h];
        const int ntok = qt*64 + wq0 + crow + h*8;
        const size_t base = ((size_t)(bb*NSEQ) + ntok)*DMOD + hh*64 + ccol;
        #pragma unroll
        for (int nt = 0; nt < 8; nt++) {
            const float x0 = o[nt][h*2]   * inv;
            const float x1 = o[nt][h*2+1] * inv;
            *(uint32_t*)(Oh + base + nt*8) = pack_bf16x2(x0, x1);
            *(uint32_t*)(Ol + base + nt*8) = pack_bf16x2(bf16_res(x0), bf16_res(x1));
        }
    }
}

// ---------------------------------------------------------------------------
extern "C" void kernel_launch(void* const* d_in, const int* in_sizes, int n_in,
                              void* d_out, int out_size) {
    const float* queries = (const float*)d_in[0];
    const float* keys    = (const float*)d_in[1];
    const float* values  = (const float*)d_in[2];
    const int*   vlen    = (const int*)  d_in[3];
    const float* Wq      = (const float*)d_in[4];
    const float* Wk      = (const float*)d_in[5];
    const float* Wv      = (const float*)d_in[6];
    const float* Wo      = (const float*)d_in[7];
    float* out = (float*)d_out;

    __nv_bfloat16 *pAh, *pAl, *pWth, *pWtl, *pQh, *pQl, *pKh, *pKl, *pVh, *pVl;
    cudaGetSymbolAddress((void**)&pAh,  g_Ah);
    cudaGetSymbolAddress((void**)&pAl,  g_Al);
    cudaGetSymbolAddress((void**)&pWth, g_Wth);
    cudaGetSymbolAddress((void**)&pWtl, g_Wtl);
    cudaGetSymbolAddress((void**)&pQh,  g_Qh);
    cudaGetSymbolAddress((void**)&pQl,  g_Ql);
    cudaGetSymbolAddress((void**)&pKh,  g_Kh);
    cudaGetSymbolAddress((void**)&pKl,  g_Kl);
    cudaGetSymbolAddress((void**)&pVh,  g_Vth);
    cudaGetSymbolAddress((void**)&pVl,  g_Vtl);

    cudaFuncSetAttribute(gemm_mma_kernel, cudaFuncAttributeMaxDynamicSharedMemorySize, GSMEM_SZ);
    cudaFuncSetAttribute(attn_mma_kernel, cudaFuncAttributeMaxDynamicSharedMemorySize, ASMEM);

    const int n4 = MROWS*DMOD/4;
    const size_t AD = (size_t)MROWS*DMOD;

    // 1. split all four weights (independent of data)
    wsplit_all<<<dim3(DMOD/32, DMOD/32, 4), dim3(32, 8)>>>(Wq, Wk, Wv, Wo, pWth, pWtl);
    // 2. split all three activations
    asplit_all<<<dim3(n4/256, 1, 3), 256>>>((const float4*)queries, (const float4*)keys,
                                            (const float4*)values, (uint2*)pAh, (uint2*)pAl, n4);
    // 3. Q/K/V projections in one launch (grid.z = 3)
    GemmBatch qkv;
    qkv.j[0] = { pAh,        pAl,        pWth,        pWtl,        nullptr, pQh, pQl, 1, 0.125f };
    qkv.j[1] = { pAh + AD,   pAl + AD,   pWth + DD,   pWtl + DD,   nullptr, pKh, pKl, 1, 1.0f };
    qkv.j[2] = { pAh + 2*AD, pAl + 2*AD, pWth + 2*DD, pWtl + 2*DD, nullptr, pVh, pVl, 2, 1.0f };
    gemm_mma_kernel<<<dim3(DMOD/128, MROWS/128, 3), 256, GSMEM_SZ>>>(qkv);

    // 4. attention: writes split output into g_Ah/g_Al slot 0
    attn_mma_kernel<<<dim3(NSEQ/64, BSZ*NH), 128, ASMEM>>>(pQh, pQl, pKh, pKl, pVh, pVl,
                                                           vlen, pAh, pAl);

    // 5. output projection
    GemmBatch ob;
    ob.j[0] = { pAh, pAl, pWth + 3*DD, pWtl + 3*DD, out, nullptr, nullptr, 0, 1.0f };
    ob.j[1] = ob.j[0]; ob.j[2] = ob.j[0];
    gemm_mma_kernel<<<dim3(DMOD/128, MROWS/128, 1), 256, GSMEM_SZ>>>(ob);
}

// round 7
// speedup vs baseline: 2.6828x; 1.0774x over previous
#include <cuda_runtime.h>
#include <cuda_bf16.h>
#include <cstdint>

#define BSZ   2
#define NSEQ  2048
#define DMOD  1024
#define NH    16
#define DHD   64
#define MROWS (BSZ*NSEQ)
#define DD    (DMOD*DMOD)

// ---------------- device scratch (no allocations allowed) ----------------
__device__ __nv_bfloat16 g_Ah[3*MROWS*DMOD];   // slot z per input; slot0 reused by attn out
__device__ __nv_bfloat16 g_Al[3*MROWS*DMOD];
__device__ __nv_bfloat16 g_Wth[4*DD];          // Wq, Wk, Wv, Wo (transposed, split)
__device__ __nv_bfloat16 g_Wtl[4*DD];
__device__ __nv_bfloat16 g_Qh[MROWS*DMOD];     // [bh][n][dh]
__device__ __nv_bfloat16 g_Ql[MROWS*DMOD];
__device__ __nv_bfloat16 g_Kh[MROWS*DMOD];     // [bh][n][dh]
__device__ __nv_bfloat16 g_Kl[MROWS*DMOD];
__device__ __nv_bfloat16 g_Vth[MROWS*DMOD];    // [bh][dh][n]  (transposed)
__device__ __nv_bfloat16 g_Vtl[MROWS*DMOD];

// ---------------- sm_80-era PTX helpers ----------------
__device__ __forceinline__ uint32_t smem_to_u32(const void* p) {
    uint32_t a;
    asm("{ .reg .u64 t; cvta.to.shared.u64 t, %1; cvt.u32.u64 %0, t; }" : "=r"(a) : "l"(p));
    return a;
}
__device__ __forceinline__ void cp_async16(uint32_t dst, const void* src) {
    asm volatile("cp.async.cg.shared.global [%0], [%1], 16;" :: "r"(dst), "l"(src));
}
__device__ __forceinline__ void cp_commit() {
    asm volatile("cp.async.commit_group;" ::: "memory");
}
template <int N>
__device__ __forceinline__ void cp_wait() {
    asm volatile("cp.async.wait_group %0;" :: "n"(N) : "memory");
}
__device__ __forceinline__ void ldsm_x4(uint32_t& r0, uint32_t& r1, uint32_t& r2,
                                        uint32_t& r3, uint32_t addr) {
    asm volatile("ldmatrix.sync.aligned.m8n8.x4.shared.b16 {%0,%1,%2,%3}, [%4];"
                 : "=r"(r0), "=r"(r1), "=r"(r2), "=r"(r3) : "r"(addr));
}
__device__ __forceinline__ void mma16816(float* c, uint32_t a0, uint32_t a1,
                                         uint32_t a2, uint32_t a3,
                                         uint32_t b0, uint32_t b1) {
    asm volatile("mma.sync.aligned.m16n8k16.row.col.f32.bf16.bf16.f32 "
                 "{%0,%1,%2,%3}, {%4,%5,%6,%7}, {%8,%9}, {%0,%1,%2,%3};"
                 : "+f"(c[0]), "+f"(c[1]), "+f"(c[2]), "+f"(c[3])
                 : "r"(a0), "r"(a1), "r"(a2), "r"(a3), "r"(b0), "r"(b1));
}

// exp on the FMA pipe: exp(x) for x <= 0, ~2e-6 rel err, underflows cleanly.
__device__ __forceinline__ float fexp(float x) {
    float t = x * 1.4426950408889634f;
    t = fmaxf(t, -126.0f);
    float n = rintf(t);
    float f = t - n;
    float p = 1.3333558e-3f;
    p = fmaf(p, f, 9.6181291e-3f);
    p = fmaf(p, f, 5.5504109e-2f);
    p = fmaf(p, f, 2.4022651e-1f);
    p = fmaf(p, f, 6.9314718e-1f);
    p = fmaf(p, f, 1.0f);
    int e = (int)n;
    return p * __int_as_float((e + 127) << 23);
}

__device__ __forceinline__ uint32_t pack_bf16x2(float a, float b) {
    uint32_t ha = (uint32_t)__bfloat16_as_ushort(__float2bfloat16(a));
    uint32_t hb = (uint32_t)__bfloat16_as_ushort(__float2bfloat16(b));
    return ha | (hb << 16);
}
__device__ __forceinline__ float bf16_res(float x) {
    return x - __bfloat162float(__float2bfloat16(x));
}
#define SWZ(o) ((o) ^ (((o) >> 3) & 0x70))

// ---------------- prep kernels (fused across operands via blockIdx.z) -------
__global__ __launch_bounds__(256)
void asplit_all(const float4* __restrict__ X0, const float4* __restrict__ X1,
                const float4* __restrict__ X2, uint2* __restrict__ Xh,
                uint2* __restrict__ Xl, int n4)
{
    const int z = blockIdx.z;
    const float4* X = (z == 0) ? X0 : ((z == 1) ? X1 : X2);
    int i = blockIdx.x*256 + threadIdx.x;
    if (i >= n4) return;
    float4 v = X[i];
    float a[4] = {v.x, v.y, v.z, v.w};
    uint32_t hb[4], lb[4];
    #pragma unroll
    for (int j = 0; j < 4; j++) {
        __nv_bfloat16 h = __float2bfloat16(a[j]);
        __nv_bfloat16 l = __float2bfloat16(a[j] - __bfloat162float(h));
        hb[j] = (uint32_t)__bfloat16_as_ushort(h);
        lb[j] = (uint32_t)__bfloat16_as_ushort(l);
    }
    uint2 uh, ul;
    uh.x = hb[0] | (hb[1] << 16); uh.y = hb[2] | (hb[3] << 16);
    ul.x = lb[0] | (lb[1] << 16); ul.y = lb[2] | (lb[3] << 16);
    Xh[(size_t)z*n4 + i] = uh; Xl[(size_t)z*n4 + i] = ul;
}

__global__ __launch_bounds__(256)
void wsplit_all(const float* __restrict__ W0, const float* __restrict__ W1,
                const float* __restrict__ W2, const float* __restrict__ W3,
                __nv_bfloat16* __restrict__ Wth, __nv_bfloat16* __restrict__ Wtl)
{
    __shared__ float ts[32][33];
    const int z = blockIdx.z;
    const float* W = (z == 0) ? W0 : ((z == 1) ? W1 : ((z == 2) ? W2 : W3));
    __nv_bfloat16* th = Wth + (size_t)z*DD;
    __nv_bfloat16* tl = Wtl + (size_t)z*DD;
    const int tx = threadIdx.x, ty = threadIdx.y;
    const int gx = blockIdx.x*32, gy = blockIdx.y*32;
    #pragma unroll
    for (int i = ty; i < 32; i += 8)
        ts[i][tx] = W[(size_t)(gy+i)*DMOD + gx + tx];
    __syncthreads();
    #pragma unroll
    for (int i = ty; i < 32; i += 8) {
        float v = ts[tx][i];
        __nv_bfloat16 h = __float2bfloat16(v);
        __nv_bfloat16 l = __float2bfloat16(v - __bfloat162float(h));
        th[(size_t)(gx+i)*DMOD + gy + tx] = h;
        tl[(size_t)(gx+i)*DMOD + gy + tx] = l;
    }
}

// ---------------- mma.sync bf16-split GEMM (batched via blockIdx.z) --------
// CTA tile 128(m) x 64(n), 8 warps of 32x32, 2 CTAs/SM.
#define KC       32
#define NCHUNK   (DMOD/KC)
#define ROWB     80
#define A_TB     (128*ROWB)          // 10240
#define B_TB     (64*ROWB)           // 5120
#define STAGE_B  (2*A_TB + 2*B_TB)   // 30720
#define GSMEM_SZ (2*STAGE_B)         // 61440

struct GemmJob {
    const __nv_bfloat16 *Ah, *Al, *Bh, *Bl;
    float* C32;
    __nv_bfloat16 *Ch, *Cl;
    int mode;          // 0: fp32 [m][D]; 1: split head [bh][n][dh]; 2: split Vt [bh][dh][n]
    float alpha;
};
struct GemmBatch { GemmJob j[3]; };

__device__ __forceinline__ void issue_chunk(uint32_t sb, int stage,
    const __nv_bfloat16* __restrict__ Ah, const __nv_bfloat16* __restrict__ Al,
    const __nv_bfloat16* __restrict__ Bh, const __nv_bfloat16* __restrict__ Bl,
    int m0, int n0, int k0, int tid)
{
    const uint32_t so = sb + stage*STAGE_B;
    // A tiles: 128 rows x 4 chunks, hi+lo
    #pragma unroll
    for (int t = 0; t < 2; t++) {
        const __nv_bfloat16* src = (t ? Al : Ah) + (size_t)m0*DMOD + k0;
        #pragma unroll
        for (int i = 0; i < 2; i++) {
            int idx = i*256 + tid;          // 0..511
            int row = idx >> 2, cg = idx & 3;
            cp_async16(so + t*A_TB + row*ROWB + cg*16, src + (size_t)row*DMOD + cg*8);
        }
    }
    // B tiles: 64 rows x 4 chunks, hi+lo
    #pragma unroll
    for (int t = 0; t < 2; t++) {
        const __nv_bfloat16* src = (t ? Bl : Bh) + (size_t)n0*DMOD + k0;
        int row = tid >> 2, cg = tid & 3;
        cp_async16(so + 2*A_TB + t*B_TB + row*ROWB + cg*16, src + (size_t)row*DMOD + cg*8);
    }
}

__global__ __launch_bounds__(256, 2)
void gemm_mma_kernel(GemmBatch P)
{
    extern __shared__ char smem[];
    const uint32_t sb = smem_to_u32(smem);
    const int tid = threadIdx.x;
    const int wid = tid >> 5, lane = tid & 31;
    const int n0 = blockIdx.x * 64;
    const int m0 = blockIdx.y * 128;
    const GemmJob& J = P.j[blockIdx.z];
    const __nv_bfloat16 *Ah = J.Ah, *Al = J.Al, *Bh = J.Bh, *Bl = J.Bl;

    const int wm = (wid & 3) * 32;      // warp m offset (4 warps)
    const int wn = (wid >> 2) * 32;     // warp n offset (2 warps)

    const int a_row = lane & 15;
    const int a_kh  = lane >> 4;
    const int b_row = ((lane >> 4) << 3) + (lane & 7);
    const int b_kh  = (lane >> 3) & 1;

    float acc[2][4][4];
    #pragma unroll
    for (int mi = 0; mi < 2; mi++)
      #pragma unroll
      for (int ni = 0; ni < 4; ni++)
        #pragma unroll
        for (int r = 0; r < 4; r++) acc[mi][ni][r] = 0.f;

    issue_chunk(sb, 0, Ah, Al, Bh, Bl, m0, n0, 0, tid);
    cp_commit();

    for (int c = 0; c < NCHUNK; c++) {
        if (c + 1 < NCHUNK) {
            issue_chunk(sb, (c+1) & 1, Ah, Al, Bh, Bl, m0, n0, (c+1)*KC, tid);
            cp_commit();
            cp_wait<1>();
        } else {
            cp_wait<0>();
        }
        __syncthreads();

        const uint32_t so = sb + (c & 1)*STAGE_B;
        #pragma unroll
        for (int ks = 0; ks < 2; ks++) {
            const uint32_t koff = (ks*16 + b_kh*8) * 2;
            uint32_t bh[2][4], bl[2][4];
            #pragma unroll
            for (int np = 0; np < 2; np++) {
                uint32_t ba = so + 2*A_TB + (wn + np*16 + b_row)*ROWB + koff;
                ldsm_x4(bh[np][0], bh[np][1], bh[np][2], bh[np][3], ba);
                ldsm_x4(bl[np][0], bl[np][1], bl[np][2], bl[np][3], ba + B_TB);
            }
            const uint32_t akoff = (ks*16 + a_kh*8) * 2;
            #pragma unroll
            for (int mi = 0; mi < 2; mi++) {
                uint32_t aa = so + (wm + mi*16 + a_row)*ROWB + akoff;
                uint32_t ah0, ah1, ah2, ah3, al0, al1, al2, al3;
                ldsm_x4(ah0, ah1, ah2, ah3, aa);
                ldsm_x4(al0, al1, al2, al3, aa + A_TB);
                #pragma unroll
                for (int ni = 0; ni < 4; ni++) {
                    const int np = ni >> 1, hf = (ni & 1) * 2;
                    mma16816(acc[mi][ni], ah0, ah1, ah2, ah3, bh[np][hf], bh[np][hf+1]);
                    mma16816(acc[mi][ni], ah0, ah1, ah2, ah3, bl[np][hf], bl[np][hf+1]);
                    mma16816(acc[mi][ni], al0, al1, al2, al3, bh[np][hf], bh[np][hf+1]);
                }
            }
        }
        __syncthreads();
    }

    const int crow = lane >> 2, ccol = (lane & 3) * 2;
    const int mode = J.mode;
    const float alpha = J.alpha;
    #pragma unroll
    for (int mi = 0; mi < 2; mi++) {
      #pragma unroll
      for (int h = 0; h < 2; h++) {
        const int m = m0 + wm + mi*16 + crow + h*8;
        const int bb = m >> 11, nn = m & (NSEQ-1);
        #pragma unroll
        for (int ni = 0; ni < 4; ni++) {
            const int n = n0 + wn + ni*8 + ccol;
            float x0 = acc[mi][ni][h*2+0] * alpha;
            float x1 = acc[mi][ni][h*2+1] * alpha;
            if (mode == 0) {
                float2 v; v.x = x0; v.y = x1;
                *(float2*)(&J.C32[(size_t)m*DMOD + n]) = v;
            } else if (mode == 1) {
                const int hh = n >> 6, dh = n & 63;
                size_t base = (((size_t)(bb*NH + hh))*NSEQ + nn)*DHD + dh;
                *(uint32_t*)(J.Ch + base) = pack_bf16x2(x0, x1);
                *(uint32_t*)(J.Cl + base) = pack_bf16x2(bf16_res(x0), bf16_res(x1));
            } else {
                const int hh = n >> 6, dh = n & 63;
                size_t base = (((size_t)(bb*NH + hh))*DHD + dh)*NSEQ + nn;
                J.Ch[base]        = __float2bfloat16(x0);
                J.Ch[base + NSEQ] = __float2bfloat16(x1);
                J.Cl[base]        = __float2bfloat16(bf16_res(x0));
                J.Cl[base + NSEQ] = __float2bfloat16(bf16_res(x1));
            }
        }
      }
    }
}

// ---------------- tensor-core flash attention ----------------
// 128 threads, 64-q tile; Q fragments via direct LDG (no Q smem);
// K/V smem: 128B swizzled rows, 2 stages x {KH,KL,VH,VL}. 3 CTAs/SM.
#define AKT   64
#define ATILE 8192                   // 64 rows x 128 B
#define ASMEM (8*ATILE)              // 65536

__device__ __forceinline__ void attn_load_kv(uint32_t sb, int stage,
    const __nv_bfloat16* __restrict__ Kh, const __nv_bfloat16* __restrict__ Kl,
    const __nv_bfloat16* __restrict__ Vh, const __nv_bfloat16* __restrict__ Vl,
    int bh, int k0, int tid)
{
    const __nv_bfloat16* srcs[4] = {
        Kh + ((size_t)bh*NSEQ + k0)*DHD,
        Kl + ((size_t)bh*NSEQ + k0)*DHD,
        Vh + ((size_t)bh*DHD)*NSEQ + k0,
        Vl + ((size_t)bh*DHD)*NSEQ + k0 };
    const int rstr[4] = {DHD, DHD, NSEQ, NSEQ};
    const uint32_t base = sb + stage*(4*ATILE);
    #pragma unroll
    for (int i = 0; i < 16; i++) {
        const int arr = i >> 2;
        const int idx = i*128 + tid;
        const int row = (idx >> 3) & 63;
        const int cg  = idx & 7;
        cp_async16(base + arr*ATILE + SWZ(row*128 + cg*16),
                   srcs[arr] + (size_t)row*rstr[arr] + cg*8);
    }
}

__global__ __launch_bounds__(128, 3)
void attn_mma_kernel(const __nv_bfloat16* __restrict__ Qh, const __nv_bfloat16* __restrict__ Ql,
                     const __nv_bfloat16* __restrict__ Kh, const __nv_bfloat16* __restrict__ Kl,
                     const __nv_bfloat16* __restrict__ Vh, const __nv_bfloat16* __restrict__ Vl,
                     const int* __restrict__ vlen,
                     __nv_bfloat16* __restrict__ Oh, __nv_bfloat16* __restrict__ Ol)
{
    extern __shared__ char smem[];
    const uint32_t sb = smem_to_u32(smem);
    const int tid = threadIdx.x, wid = tid >> 5, lane = tid & 31;
    const int qt = blockIdx.x, bh = blockIdx.y;
    const int vl = vlen[bh];
    const int ntiles = (vl + AKT - 1) / AKT;
    const int wq0 = wid * 16;

    const int crow = lane >> 2, ccol = (lane & 3) * 2;
    const int b_row = ((lane >> 4) << 3) + (lane & 7);
    const int b_kh = (lane >> 3) & 1;

    // KV stage 0 prefetch first, then Q fragments straight from global.
    attn_load_kv(sb, 0, Kh, Kl, Vh, Vl, bh, 0, tid);
    cp_commit();

    uint32_t qfh[4][4], qfl[4][4];
    {
        const __nv_bfloat16* qh = Qh + ((size_t)bh*NSEQ + qt*64 + wq0)*DHD;
        const __nv_bfloat16* ql = Ql + ((size_t)bh*NSEQ + qt*64 + wq0)*DHD;
        #pragma unroll
        for (int ks = 0; ks < 4; ks++) {
            const int col = ks*16 + ccol;
            qfh[ks][0] = *(const uint32_t*)(qh + (size_t)crow*DHD + col);
            qfh[ks][1] = *(const uint32_t*)(qh + (size_t)(crow+8)*DHD + col);
            qfh[ks][2] = *(const uint32_t*)(qh + (size_t)crow*DHD + col + 8);
            qfh[ks][3] = *(const uint32_t*)(qh + (size_t)(crow+8)*DHD + col + 8);
            qfl[ks][0] = *(const uint32_t*)(ql + (size_t)crow*DHD + col);
            qfl[ks][1] = *(const uint32_t*)(ql + (size_t)(crow+8)*DHD + col);
            qfl[ks][2] = *(const uint32_t*)(ql + (size_t)crow*DHD + col + 8);
            qfl[ks][3] = *(const uint32_t*)(ql + (size_t)(crow+8)*DHD + col + 8);
        }
    }

    float o[8][4];
    float m_i[2] = {-1e30f, -1e30f}, l_i[2] = {0.f, 0.f};
    #pragma unroll
    for (int nt = 0; nt < 8; nt++)
        #pragma unroll
        for (int r = 0; r < 4; r++) o[nt][r] = 0.f;

    for (int kt = 0; kt < ntiles; kt++) {
        if (kt + 1 < ntiles) {
            attn_load_kv(sb, (kt+1) & 1, Kh, Kl, Vh, Vl, bh, (kt+1)*AKT, tid);
            cp_commit();
            cp_wait<1>();
        } else {
            cp_wait<0>();
        }
        __syncthreads();

        const uint32_t soK = sb + (kt & 1)*(4*ATILE);   // KH; +AT=KL, +2AT=VH, +3AT=VL

        // ---- S = Q . K^T (hi/lo split, fp32 acc) ----
        float s[8][4];
        #pragma unroll
        for (int nt = 0; nt < 8; nt++)
            #pragma unroll
            for (int r = 0; r < 4; r++) s[nt][r] = 0.f;

        #pragma unroll
        for (int ks = 0; ks < 4; ks++) {
            const uint32_t koff = ks*32 + b_kh*16;
            #pragma unroll
            for (int np = 0; np < 4; np++) {
                const uint32_t ro = (np*16 + b_row)*128 + koff;
                const uint32_t ka = soK + SWZ(ro);
                uint32_t kfh[4], kfl[4];
                ldsm_x4(kfh[0], kfh[1], kfh[2], kfh[3], ka);
                ldsm_x4(kfl[0], kfl[1], kfl[2], kfl[3], ka + ATILE);
                #pragma unroll
                for (int t = 0; t < 2; t++) {
                    float* sc = s[np*2 + t];
                    mma16816(sc, qfh[ks][0], qfh[ks][1], qfh[ks][2], qfh[ks][3], kfh[t*2], kfh[t*2+1]);
                    mma16816(sc, qfh[ks][0], qfh[ks][1], qfh[ks][2], qfh[ks][3], kfl[t*2], kfl[t*2+1]);
                    mma16816(sc, qfl[ks][0], qfl[ks][1], qfl[ks][2], qfl[ks][3], kfh[t*2], kfh[t*2+1]);
                }
            }
        }

        // ---- masking + online softmax (p stays in s[][] as fp32) ----
        const int kb = kt * AKT;
        const bool full = (kb + AKT <= vl);
        #pragma unroll
        for (int h = 0; h < 2; h++) {
            if (!full) {
                #pragma unroll
                for (int nt = 0; nt < 8; nt++) {
                    const int c0 = kb + nt*8 + ccol;
                    if (c0     >= vl) s[nt][h*2]   = -1e30f;
                    if (c0 + 1 >= vl) s[nt][h*2+1] = -1e30f;
                }
            }
            float rmax = -1e30f;
            #pragma unroll
            for (int nt = 0; nt < 8; nt++)
                rmax = fmaxf(rmax, fmaxf(s[nt][h*2], s[nt][h*2+1]));
            rmax = fmaxf(rmax, __shfl_xor_sync(0xffffffffu, rmax, 1));
            rmax = fmaxf(rmax, __shfl_xor_sync(0xffffffffu, rmax, 2));
            const float m_new = fmaxf(m_i[h], rmax);
            const float rsc = fexp(m_i[h] - m_new);
            m_i[h] = m_new;
            float rsum = 0.f;
            #pragma unroll
            for (int nt = 0; nt < 8; nt++) {
                const float p0 = fexp(s[nt][h*2]   - m_new);
                const float p1 = fexp(s[nt][h*2+1] - m_new);
                s[nt][h*2]   = p0;
                s[nt][h*2+1] = p1;
                rsum += p0 + p1;
            }
            rsum += __shfl_xor_sync(0xffffffffu, rsum, 1);
            rsum += __shfl_xor_sync(0xffffffffu, rsum, 2);
            l_i[h] = l_i[h]*rsc + rsum;
            #pragma unroll
            for (int nt = 0; nt < 8; nt++) { o[nt][h*2] *= rsc; o[nt][h*2+1] *= rsc; }
        }

        // ---- O += P . V : P fragments built in registers from S C-fragments ----
        #pragma unroll
        for (int ks = 0; ks < 4; ks++) {
            const int t0 = 2*ks, t1 = 2*ks + 1;
            const uint32_t ph0 = pack_bf16x2(s[t0][0], s[t0][1]);
            const uint32_t ph1 = pack_bf16x2(s[t0][2], s[t0][3]);
            const uint32_t ph2 = pack_bf16x2(s[t1][0], s[t1][1]);
            const uint32_t ph3 = pack_bf16x2(s[t1][2], s[t1][3]);
            const uint32_t pl0 = pack_bf16x2(bf16_res(s[t0][0]), bf16_res(s[t0][1]));
            const uint32_t pl1 = pack_bf16x2(bf16_res(s[t0][2]), bf16_res(s[t0][3]));
            const uint32_t pl2 = pack_bf16x2(bf16_res(s[t1][0]), bf16_res(s[t1][1]));
            const uint32_t pl3 = pack_bf16x2(bf16_res(s[t1][2]), bf16_res(s[t1][3]));
            const uint32_t koff = ks*32 + b_kh*16;
            #pragma unroll
            for (int np = 0; np < 4; np++) {
                const uint32_t ro = (np*16 + b_row)*128 + koff;
                const uint32_t va = soK + 2*ATILE + SWZ(ro);
                uint32_t vfh[4], vfl[4];
                ldsm_x4(vfh[0], vfh[1], vfh[2], vfh[3], va);
                ldsm_x4(vfl[0], vfl[1], vfl[2], vfl[3], va + ATILE);
                #pragma unroll
                for (int t = 0; t < 2; t++) {
                    float* oc = o[np*2 + t];
                    mma16816(oc, ph0, ph1, ph2, ph3, vfh[t*2], vfh[t*2+1]);
                    mma16816(oc, ph0, ph1, ph2, ph3, vfl[t*2], vfl[t*2+1]);
                    mma16816(oc, pl0, pl1, pl2, pl3, vfh[t*2], vfh[t*2+1]);
                }
            }
        }
        __syncthreads();   // stage (kt&1) fully consumed before it is refilled
    }

    // ---- epilogue: normalize, split, write as final-GEMM A operand ----
    const int bb = bh >> 4, hh = bh & 15;
    #pragma unroll
    for (int h = 0; h < 2; h++) {
        const float inv = 1.0f / l_i[h];
        const int ntok = qt*64 + wq0 + crow + h*8;
        const size_t base = ((size_t)(bb*NSEQ) + ntok)*DMOD + hh*64 + ccol;
        #pragma unroll
        for (int nt = 0; nt < 8; nt++) {
            const float x0 = o[nt][h*2]   * inv;
            const float x1 = o[nt][h*2+1] * inv;
            *(uint32_t*)(Oh + base + nt*8) = pack_bf16x2(x0, x1);
            *(uint32_t*)(Ol + base + nt*8) = pack_bf16x2(bf16_res(x0), bf16_res(x1));
        }
    }
}

// ---------------------------------------------------------------------------
extern "C" void kernel_launch(void* const* d_in, const int* in_sizes, int n_in,
                              void* d_out, int out_size) {
    const float* queries = (const float*)d_in[0];
    const float* keys    = (const float*)d_in[1];
    const float* values  = (const float*)d_in[2];
    const int*   vlen    = (const int*)  d_in[3];
    const float* Wq      = (const float*)d_in[4];
    const float* Wk      = (const float*)d_in[5];
    const float* Wv      = (const float*)d_in[6];
    const float* Wo      = (const float*)d_in[7];
    float* out = (float*)d_out;

    __nv_bfloat16 *pAh, *pAl, *pWth, *pWtl, *pQh, *pQl, *pKh, *pKl, *pVh, *pVl;
    cudaGetSymbolAddress((void**)&pAh,  g_Ah);
    cudaGetSymbolAddress((void**)&pAl,  g_Al);
    cudaGetSymbolAddress((void**)&pWth, g_Wth);
    cudaGetSymbolAddress((void**)&pWtl, g_Wtl);
    cudaGetSymbolAddress((void**)&pQh,  g_Qh);
    cudaGetSymbolAddress((void**)&pQl,  g_Ql);
    cudaGetSymbolAddress((void**)&pKh,  g_Kh);
    cudaGetSymbolAddress((void**)&pKl,  g_Kl);
    cudaGetSymbolAddress((void**)&pVh,  g_Vth);
    cudaGetSymbolAddress((void**)&pVl,  g_Vtl);

    cudaFuncSetAttribute(gemm_mma_kernel, cudaFuncAttributeMaxDynamicSharedMemorySize, GSMEM_SZ);
    cudaFuncSetAttribute(attn_mma_kernel, cudaFuncAttributeMaxDynamicSharedMemorySize, ASMEM);

    const int n4 = MROWS*DMOD/4;
    const size_t AD = (size_t)MROWS*DMOD;

    wsplit_all<<<dim3(DMOD/32, DMOD/32, 4), dim3(32, 8)>>>(Wq, Wk, Wv, Wo, pWth, pWtl);
    asplit_all<<<dim3(n4/256, 1, 3), 256>>>((const float4*)queries, (const float4*)keys,
                                            (const float4*)values, (uint2*)pAh, (uint2*)pAl, n4);

    GemmBatch qkv;
    qkv.j[0] = { pAh,        pAl,        pWth,        pWtl,        nullptr, pQh, pQl, 1, 0.125f };
    qkv.j[1] = { pAh + AD,   pAl + AD,   pWth + DD,   pWtl + DD,   nullptr, pKh, pKl, 1, 1.0f };
    qkv.j[2] = { pAh + 2*AD, pAl + 2*AD, pWth + 2*DD, pWtl + 2*DD, nullptr, pVh, pVl, 2, 1.0f };
    gemm_mma_kernel<<<dim3(DMOD/64, MROWS/128, 3), 256, GSMEM_SZ>>>(qkv);

    attn_mma_kernel<<<dim3(NSEQ/64, BSZ*NH), 128, ASMEM>>>(pQh, pQl, pKh, pKl, pVh, pVl,
                                                           vlen, pAh, pAl);

    GemmBatch ob;
    ob.j[0] = { pAh, pAl, pWth + 3*DD, pWtl + 3*DD, out, nullptr, nullptr, 0, 1.0f };
    ob.j[1] = ob.j[0]; ob.j[2] = ob.j[0];
    gemm_mma_kernel<<<dim3(DMOD/64, MROWS/128, 1), 256, GSMEM_SZ>>>(ob);
}

// round 8
// speedup vs baseline: 2.8500x; 1.0623x over previous
#include <cuda_runtime.h>
#include <cuda_bf16.h>
#include <cstdint>

#define BSZ   2
#define NSEQ  2048
#define DMOD  1024
#define NH    16
#define DHD   64
#define MROWS (BSZ*NSEQ)
#define DD    (DMOD*DMOD)

// ---------------- device scratch (no allocations allowed) ----------------
__device__ __nv_bfloat16 g_Ah[3*MROWS*DMOD];
__device__ __nv_bfloat16 g_Al[3*MROWS*DMOD];
__device__ __nv_bfloat16 g_Wth[4*DD];
__device__ __nv_bfloat16 g_Wtl[4*DD];
__device__ __nv_bfloat16 g_Qh[MROWS*DMOD];     // [bh][n][dh], pre-scaled by 0.125*log2e
__device__ __nv_bfloat16 g_Ql[MROWS*DMOD];
__device__ __nv_bfloat16 g_Kh[MROWS*DMOD];     // [bh][n][dh]
__device__ __nv_bfloat16 g_Kl[MROWS*DMOD];
__device__ __nv_bfloat16 g_Vth[MROWS*DMOD];    // [bh][dh][n]
__device__ __nv_bfloat16 g_Vtl[MROWS*DMOD];

// ---------------- PTX helpers ----------------
__device__ __forceinline__ uint32_t smem_to_u32(const void* p) {
    uint32_t a;
    asm("{ .reg .u64 t; cvta.to.shared.u64 t, %1; cvt.u32.u64 %0, t; }" : "=r"(a) : "l"(p));
    return a;
}
__device__ __forceinline__ void cp_async16(uint32_t dst, const void* src) {
    asm volatile("cp.async.cg.shared.global [%0], [%1], 16;" :: "r"(dst), "l"(src));
}
__device__ __forceinline__ void cp_commit() {
    asm volatile("cp.async.commit_group;" ::: "memory");
}
template <int N>
__device__ __forceinline__ void cp_wait() {
    asm volatile("cp.async.wait_group %0;" :: "n"(N) : "memory");
}
__device__ __forceinline__ void ldsm_x4(uint32_t& r0, uint32_t& r1, uint32_t& r2,
                                        uint32_t& r3, uint32_t addr) {
    asm volatile("ldmatrix.sync.aligned.m8n8.x4.shared.b16 {%0,%1,%2,%3}, [%4];"
                 : "=r"(r0), "=r"(r1), "=r"(r2), "=r"(r3) : "r"(addr));
}
__device__ __forceinline__ void mma16816(float* c, uint32_t a0, uint32_t a1,
                                         uint32_t a2, uint32_t a3,
                                         uint32_t b0, uint32_t b1) {
    asm volatile("mma.sync.aligned.m16n8k16.row.col.f32.bf16.bf16.f32 "
                 "{%0,%1,%2,%3}, {%4,%5,%6,%7}, {%8,%9}, {%0,%1,%2,%3};"
                 : "+f"(c[0]), "+f"(c[1]), "+f"(c[2]), "+f"(c[3])
                 : "r"(a0), "r"(a1), "r"(a2), "r"(a3), "r"(b0), "r"(b1));
}

// exp2(x) for x <= 0 (inputs already in log2 domain), ~2e-6 rel err.
__device__ __forceinline__ float fexp2(float t) {
    t = fmaxf(t, -126.0f);
    float n = rintf(t);
    float f = t - n;
    float p = 1.3333558e-3f;
    p = fmaf(p, f, 9.6181291e-3f);
    p = fmaf(p, f, 5.5504109e-2f);
    p = fmaf(p, f, 2.4022651e-1f);
    p = fmaf(p, f, 6.9314718e-1f);
    p = fmaf(p, f, 1.0f);
    int e = (int)n;
    return p * __int_as_float((e + 127) << 23);
}

// single-instruction bf16x2 pack: lo = a, hi = b
__device__ __forceinline__ uint32_t pack2(float a, float b) {
    uint32_t r;
    asm("cvt.rn.bf16x2.f32 %0, %1, %2;" : "=r"(r) : "f"(b), "f"(a));
    return r;
}
// residual pair for (a, b) whose hi-pack is hpk
__device__ __forceinline__ uint32_t res_pack(uint32_t hpk, float a, float b) {
    float ha = __int_as_float(hpk << 16);
    float hb = __int_as_float(hpk & 0xffff0000u);
    return pack2(a - ha, b - hb);
}
__device__ __forceinline__ float bf16_res(float x) {
    return x - __bfloat162float(__float2bfloat16(x));
}
#define SWZ(o) ((o) ^ (((o) >> 3) & 0x70))

// ---------------- prep kernels ----------------
__global__ __launch_bounds__(256)
void asplit_all(const float4* __restrict__ X0, const float4* __restrict__ X1,
                const float4* __restrict__ X2, uint2* __restrict__ Xh,
                uint2* __restrict__ Xl, int n4)
{
    const int z = blockIdx.z;
    const float4* X = (z == 0) ? X0 : ((z == 1) ? X1 : X2);
    int i = blockIdx.x*256 + threadIdx.x;
    if (i >= n4) return;
    float4 v = X[i];
    uint2 uh, ul;
    uh.x = pack2(v.x, v.y); uh.y = pack2(v.z, v.w);
    ul.x = res_pack(uh.x, v.x, v.y); ul.y = res_pack(uh.y, v.z, v.w);
    Xh[(size_t)z*n4 + i] = uh; Xl[(size_t)z*n4 + i] = ul;
}

__global__ __launch_bounds__(256)
void wsplit_all(const float* __restrict__ W0, const float* __restrict__ W1,
                const float* __restrict__ W2, const float* __restrict__ W3,
                __nv_bfloat16* __restrict__ Wth, __nv_bfloat16* __restrict__ Wtl)
{
    __shared__ float ts[32][33];
    const int z = blockIdx.z;
    const float* W = (z == 0) ? W0 : ((z == 1) ? W1 : ((z == 2) ? W2 : W3));
    __nv_bfloat16* th = Wth + (size_t)z*DD;
    __nv_bfloat16* tl = Wtl + (size_t)z*DD;
    const int tx = threadIdx.x, ty = threadIdx.y;
    const int gx = blockIdx.x*32, gy = blockIdx.y*32;
    #pragma unroll
    for (int i = ty; i < 32; i += 8)
        ts[i][tx] = W[(size_t)(gy+i)*DMOD + gx + tx];
    __syncthreads();
    #pragma unroll
    for (int i = ty; i < 32; i += 8) {
        float v = ts[tx][i];
        __nv_bfloat16 h = __float2bfloat16(v);
        th[(size_t)(gx+i)*DMOD + gy + tx] = h;
        tl[(size_t)(gx+i)*DMOD + gy + tx] = __float2bfloat16(v - __bfloat162float(h));
    }
}

// ---------------- mma.sync bf16-split GEMM ----------------
// CTA 128(m) x 64(n), 4 warps of 64x32 (2x2), 3 CTAs/SM.
#define KC       32
#define NCHUNK   (DMOD/KC)
#define ROWB     80
#define A_TB     (128*ROWB)          // 10240
#define B_TB     (64*ROWB)           // 5120
#define STAGE_B  (2*A_TB + 2*B_TB)   // 30720
#define GSMEM_SZ (2*STAGE_B)         // 61440

struct GemmJob {
    const __nv_bfloat16 *Ah, *Al, *Bh, *Bl;
    float* C32;
    __nv_bfloat16 *Ch, *Cl;
    int mode;
    float alpha;
};
struct GemmBatch { GemmJob j[3]; };

__device__ __forceinline__ void issue_chunk(uint32_t sb, int stage,
    const __nv_bfloat16* __restrict__ Ah, const __nv_bfloat16* __restrict__ Al,
    const __nv_bfloat16* __restrict__ Bh, const __nv_bfloat16* __restrict__ Bl,
    int m0, int n0, int k0, int tid)
{
    const uint32_t so = sb + stage*STAGE_B;
    #pragma unroll
    for (int t = 0; t < 2; t++) {
        const __nv_bfloat16* src = (t ? Al : Ah) + (size_t)m0*DMOD + k0;
        #pragma unroll
        for (int i = 0; i < 4; i++) {
            int idx = i*128 + tid;          // 0..511
            int row = idx >> 2, cg = idx & 3;
            cp_async16(so + t*A_TB + row*ROWB + cg*16, src + (size_t)row*DMOD + cg*8);
        }
    }
    #pragma unroll
    for (int t = 0; t < 2; t++) {
        const __nv_bfloat16* src = (t ? Bl : Bh) + (size_t)n0*DMOD + k0;
        #pragma unroll
        for (int i = 0; i < 2; i++) {
            int idx = i*128 + tid;          // 0..255
            int row = idx >> 2, cg = idx & 3;
            cp_async16(so + 2*A_TB + t*B_TB + row*ROWB + cg*16, src + (size_t)row*DMOD + cg*8);
        }
    }
}

__global__ __launch_bounds__(128, 3)
void gemm_mma_kernel(GemmBatch P)
{
    extern __shared__ char smem[];
    const uint32_t sb = smem_to_u32(smem);
    const int tid = threadIdx.x;
    const int wid = tid >> 5, lane = tid & 31;
    const int n0 = blockIdx.x * 64;
    const int m0 = blockIdx.y * 128;
    const GemmJob& J = P.j[blockIdx.z];
    const __nv_bfloat16 *Ah = J.Ah, *Al = J.Al, *Bh = J.Bh, *Bl = J.Bl;

    const int wm = (wid & 1) * 64;
    const int wn = (wid >> 1) * 32;

    const int a_row = lane & 15;
    const int a_kh  = lane >> 4;
    const int b_row = ((lane >> 4) << 3) + (lane & 7);
    const int b_kh  = (lane >> 3) & 1;

    float acc[4][4][4];
    #pragma unroll
    for (int mi = 0; mi < 4; mi++)
      #pragma unroll
      for (int ni = 0; ni < 4; ni++)
        #pragma unroll
        for (int r = 0; r < 4; r++) acc[mi][ni][r] = 0.f;

    issue_chunk(sb, 0, Ah, Al, Bh, Bl, m0, n0, 0, tid);
    cp_commit();

    for (int c = 0; c < NCHUNK; c++) {
        if (c + 1 < NCHUNK) {
            issue_chunk(sb, (c+1) & 1, Ah, Al, Bh, Bl, m0, n0, (c+1)*KC, tid);
            cp_commit();
            cp_wait<1>();
        } else {
            cp_wait<0>();
        }
        __syncthreads();

        const uint32_t so = sb + (c & 1)*STAGE_B;
        #pragma unroll
        for (int ks = 0; ks < 2; ks++) {
            const uint32_t koff = (ks*16 + b_kh*8) * 2;
            uint32_t bh[2][4], bl[2][4];
            #pragma unroll
            for (int np = 0; np < 2; np++) {
                uint32_t ba = so + 2*A_TB + (wn + np*16 + b_row)*ROWB + koff;
                ldsm_x4(bh[np][0], bh[np][1], bh[np][2], bh[np][3], ba);
                ldsm_x4(bl[np][0], bl[np][1], bl[np][2], bl[np][3], ba + B_TB);
            }
            const uint32_t akoff = (ks*16 + a_kh*8) * 2;
            #pragma unroll
            for (int mi = 0; mi < 4; mi++) {
                uint32_t aa = so + (wm + mi*16 + a_row)*ROWB + akoff;
                uint32_t ah0, ah1, ah2, ah3, al0, al1, al2, al3;
                ldsm_x4(ah0, ah1, ah2, ah3, aa);
                ldsm_x4(al0, al1, al2, al3, aa + A_TB);
                #pragma unroll
                for (int ni = 0; ni < 4; ni++) {
                    const int np = ni >> 1, hf = (ni & 1) * 2;
                    mma16816(acc[mi][ni], ah0, ah1, ah2, ah3, bh[np][hf], bh[np][hf+1]);
                    mma16816(acc[mi][ni], ah0, ah1, ah2, ah3, bl[np][hf], bl[np][hf+1]);
                    mma16816(acc[mi][ni], al0, al1, al2, al3, bh[np][hf], bh[np][hf+1]);
                }
            }
        }
        __syncthreads();
    }

    const int crow = lane >> 2, ccol = (lane & 3) * 2;
    const int mode = J.mode;
    const float alpha = J.alpha;
    #pragma unroll
    for (int mi = 0; mi < 4; mi++) {
      #pragma unroll
      for (int h = 0; h < 2; h++) {
        const int m = m0 + wm + mi*16 + crow + h*8;
        const int bb = m >> 11, nn = m & (NSEQ-1);
        #pragma unroll
        for (int ni = 0; ni < 4; ni++) {
            const int n = n0 + wn + ni*8 + ccol;
            float x0 = acc[mi][ni][h*2+0] * alpha;
            float x1 = acc[mi][ni][h*2+1] * alpha;
            if (mode == 0) {
                float2 v; v.x = x0; v.y = x1;
                *(float2*)(&J.C32[(size_t)m*DMOD + n]) = v;
            } else if (mode == 1) {
                const int hh = n >> 6, dh = n & 63;
                size_t base = (((size_t)(bb*NH + hh))*NSEQ + nn)*DHD + dh;
                uint32_t hp = pack2(x0, x1);
                *(uint32_t*)(J.Ch + base) = hp;
                *(uint32_t*)(J.Cl + base) = res_pack(hp, x0, x1);
            } else {
                const int hh = n >> 6, dh = n & 63;
                size_t base = (((size_t)(bb*NH + hh))*DHD + dh)*NSEQ + nn;
                J.Ch[base]        = __float2bfloat16(x0);
                J.Ch[base + NSEQ] = __float2bfloat16(x1);
                J.Cl[base]        = __float2bfloat16(bf16_res(x0));
                J.Cl[base + NSEQ] = __float2bfloat16(bf16_res(x1));
            }
        }
      }
    }
}

// ---------------- tensor-core flash attention ----------------
#define AKT   64
#define ATILE 8192
#define ASMEM (8*ATILE)

__device__ __forceinline__ void attn_load_kv(uint32_t sb, int stage,
    const __nv_bfloat16* __restrict__ Kh, const __nv_bfloat16* __restrict__ Kl,
    const __nv_bfloat16* __restrict__ Vh, const __nv_bfloat16* __restrict__ Vl,
    int bh, int k0, int tid)
{
    const __nv_bfloat16* srcs[4] = {
        Kh + ((size_t)bh*NSEQ + k0)*DHD,
        Kl + ((size_t)bh*NSEQ + k0)*DHD,
        Vh + ((size_t)bh*DHD)*NSEQ + k0,
        Vl + ((size_t)bh*DHD)*NSEQ + k0 };
    const int rstr[4] = {DHD, DHD, NSEQ, NSEQ};
    const uint32_t base = sb + stage*(4*ATILE);
    #pragma unroll
    for (int i = 0; i < 16; i++) {
        const int arr = i >> 2;
        const int idx = i*128 + tid;
        const int row = (idx >> 3) & 63;
        const int cg  = idx & 7;
        cp_async16(base + arr*ATILE + SWZ(row*128 + cg*16),
                   srcs[arr] + (size_t)row*rstr[arr] + cg*8);
    }
}

__global__ __launch_bounds__(128, 3)
void attn_mma_kernel(const __nv_bfloat16* __restrict__ Qh, const __nv_bfloat16* __restrict__ Ql,
                     const __nv_bfloat16* __restrict__ Kh, const __nv_bfloat16* __restrict__ Kl,
                     const __nv_bfloat16* __restrict__ Vh, const __nv_bfloat16* __restrict__ Vl,
                     const int* __restrict__ vlen,
                     __nv_bfloat16* __restrict__ Oh, __nv_bfloat16* __restrict__ Ol)
{
    extern __shared__ char smem[];
    const uint32_t sb = smem_to_u32(smem);
    const int tid = threadIdx.x, wid = tid >> 5, lane = tid & 31;
    const int bh = blockIdx.x, qt = blockIdx.y;   // bh fastest: waves mix valid_lens
    const int vl = vlen[bh];
    const int ntiles = (vl + AKT - 1) / AKT;
    const int wq0 = wid * 16;

    const int crow = lane >> 2, ccol = (lane & 3) * 2;
    const int b_row = ((lane >> 4) << 3) + (lane & 7);
    const int b_kh = (lane >> 3) & 1;

    attn_load_kv(sb, 0, Kh, Kl, Vh, Vl, bh, 0, tid);
    cp_commit();

    uint32_t qfh[4][4], qfl[4][4];
    {
        const __nv_bfloat16* qh = Qh + ((size_t)bh*NSEQ + qt*64 + wq0)*DHD;
        const __nv_bfloat16* ql = Ql + ((size_t)bh*NSEQ + qt*64 + wq0)*DHD;
        #pragma unroll
        for (int ks = 0; ks < 4; ks++) {
            const int col = ks*16 + ccol;
            qfh[ks][0] = *(const uint32_t*)(qh + (size_t)crow*DHD + col);
            qfh[ks][1] = *(const uint32_t*)(qh + (size_t)(crow+8)*DHD + col);
            qfh[ks][2] = *(const uint32_t*)(qh + (size_t)crow*DHD + col + 8);
            qfh[ks][3] = *(const uint32_t*)(qh + (size_t)(crow+8)*DHD + col + 8);
            qfl[ks][0] = *(const uint32_t*)(ql + (size_t)crow*DHD + col);
            qfl[ks][1] = *(const uint32_t*)(ql + (size_t)(crow+8)*DHD + col);
            qfl[ks][2] = *(const uint32_t*)(ql + (size_t)crow*DHD + col + 8);
            qfl[ks][3] = *(const uint32_t*)(ql + (size_t)(crow+8)*DHD + col + 8);
        }
    }

    float o[8][4];
    float m_i[2] = {-1e30f, -1e30f}, l_i[2] = {0.f, 0.f};
    #pragma unroll
    for (int nt = 0; nt < 8; nt++)
        #pragma unroll
        for (int r = 0; r < 4; r++) o[nt][r] = 0.f;

    for (int kt = 0; kt < ntiles; kt++) {
        if (kt + 1 < ntiles) {
            attn_load_kv(sb, (kt+1) & 1, Kh, Kl, Vh, Vl, bh, (kt+1)*AKT, tid);
            cp_commit();
            cp_wait<1>();
        } else {
            cp_wait<0>();
        }
        __syncthreads();

        const uint32_t soK = sb + (kt & 1)*(4*ATILE);

        float s[8][4];
        #pragma unroll
        for (int nt = 0; nt < 8; nt++)
            #pragma unroll
            for (int r = 0; r < 4; r++) s[nt][r] = 0.f;

        #pragma unroll
        for (int ks = 0; ks < 4; ks++) {
            const uint32_t koff = ks*32 + b_kh*16;
            #pragma unroll
            for (int np = 0; np < 4; np++) {
                const uint32_t ro = (np*16 + b_row)*128 + koff;
                const uint32_t ka = soK + SWZ(ro);
                uint32_t kfh[4], kfl[4];
                ldsm_x4(kfh[0], kfh[1], kfh[2], kfh[3], ka);
                ldsm_x4(kfl[0], kfl[1], kfl[2], kfl[3], ka + ATILE);
                #pragma unroll
                for (int t = 0; t < 2; t++) {
                    float* sc = s[np*2 + t];
                    mma16816(sc, qfh[ks][0], qfh[ks][1], qfh[ks][2], qfh[ks][3], kfh[t*2], kfh[t*2+1]);
                    mma16816(sc, qfh[ks][0], qfh[ks][1], qfh[ks][2], qfh[ks][3], kfl[t*2], kfl[t*2+1]);
                    mma16816(sc, qfl[ks][0], qfl[ks][1], qfl[ks][2], qfl[ks][3], kfh[t*2], kfh[t*2+1]);
                }
            }
        }

        // masking + online softmax in exp2 domain (log2e pre-folded into Q)
        const int kb = kt * AKT;
        const bool full = (kb + AKT <= vl);
        #pragma unroll
        for (int h = 0; h < 2; h++) {
            if (!full) {
                #pragma unroll
                for (int nt = 0; nt < 8; nt++) {
                    const int c0 = kb + nt*8 + ccol;
                    if (c0     >= vl) s[nt][h*2]   = -1e30f;
                    if (c0 + 1 >= vl) s[nt][h*2+1] = -1e30f;
                }
            }
            float rmax = -1e30f;
            #pragma unroll
            for (int nt = 0; nt < 8; nt++)
                rmax = fmaxf(rmax, fmaxf(s[nt][h*2], s[nt][h*2+1]));
            rmax = fmaxf(rmax, __shfl_xor_sync(0xffffffffu, rmax, 1));
            rmax = fmaxf(rmax, __shfl_xor_sync(0xffffffffu, rmax, 2));
            const float m_new = fmaxf(m_i[h], rmax);
            const float rsc = fexp2(m_i[h] - m_new);
            m_i[h] = m_new;
            float rsum = 0.f;
            #pragma unroll
            for (int nt = 0; nt < 8; nt++) {
                const float p0 = fexp2(s[nt][h*2]   - m_new);
                const float p1 = fexp2(s[nt][h*2+1] - m_new);
                s[nt][h*2]   = p0;
                s[nt][h*2+1] = p1;
                rsum += p0 + p1;
            }
            rsum += __shfl_xor_sync(0xffffffffu, rsum, 1);
            rsum += __shfl_xor_sync(0xffffffffu, rsum, 2);
            l_i[h] = l_i[h]*rsc + rsum;
            #pragma unroll
            for (int nt = 0; nt < 8; nt++) { o[nt][h*2] *= rsc; o[nt][h*2+1] *= rsc; }
        }

        // O += P.V with register-built P fragments (1-instr packs + bit-res)
        #pragma unroll
        for (int ks = 0; ks < 4; ks++) {
            const int t0 = 2*ks, t1 = 2*ks + 1;
            const uint32_t ph0 = pack2(s[t0][0], s[t0][1]);
            const uint32_t ph1 = pack2(s[t0][2], s[t0][3]);
            const uint32_t ph2 = pack2(s[t1][0], s[t1][1]);
            const uint32_t ph3 = pack2(s[t1][2], s[t1][3]);
            const uint32_t pl0 = res_pack(ph0, s[t0][0], s[t0][1]);
            const uint32_t pl1 = res_pack(ph1, s[t0][2], s[t0][3]);
            const uint32_t pl2 = res_pack(ph2, s[t1][0], s[t1][1]);
            const uint32_t pl3 = res_pack(ph3, s[t1][2], s[t1][3]);
            const uint32_t koff = ks*32 + b_kh*16;
            #pragma unroll
            for (int np = 0; np < 4; np++) {
                const uint32_t ro = (np*16 + b_row)*128 + koff;
                const uint32_t va = soK + 2*ATILE + SWZ(ro);
                uint32_t vfh[4], vfl[4];
                ldsm_x4(vfh[0], vfh[1], vfh[2], vfh[3], va);
                ldsm_x4(vfl[0], vfl[1], vfl[2], vfl[3], va + ATILE);
                #pragma unroll
                for (int t = 0; t < 2; t++) {
                    float* oc = o[np*2 + t];
                    mma16816(oc, ph0, ph1, ph2, ph3, vfh[t*2], vfh[t*2+1]);
                    mma16816(oc, ph0, ph1, ph2, ph3, vfl[t*2], vfl[t*2+1]);
                    mma16816(oc, pl0, pl1, pl2, pl3, vfh[t*2], vfh[t*2+1]);
                }
            }
        }
        __syncthreads();
    }

    const int bb = bh >> 4, hh = bh & 15;
    #pragma unroll
    for (int h = 0; h < 2; h++) {
        const float inv = 1.0f / l_i[h];
        const int ntok = qt*64 + wq0 + crow + h*8;
        const size_t base = ((size_t)(bb*NSEQ) + ntok)*DMOD + hh*64 + ccol;
        #pragma unroll
        for (int nt = 0; nt < 8; nt++) {
            const float x0 = o[nt][h*2]   * inv;
            const float x1 = o[nt][h*2+1] * inv;
            uint32_t hp = pack2(x0, x1);
            *(uint32_t*)(Oh + base + nt*8) = hp;
            *(uint32_t*)(Ol + base + nt*8) = res_pack(hp, x0, x1);
        }
    }
}

// ---------------------------------------------------------------------------
extern "C" void kernel_launch(void* const* d_in, const int* in_sizes, int n_in,
                              void* d_out, int out_size) {
    const float* queries = (const float*)d_in[0];
    const float* keys    = (const float*)d_in[1];
    const float* values  = (const float*)d_in[2];
    const int*   vlen    = (const int*)  d_in[3];
    const float* Wq      = (const float*)d_in[4];
    const float* Wk      = (const float*)d_in[5];
    const float* Wv      = (const float*)d_in[6];
    const float* Wo      = (const float*)d_in[7];
    float* out = (float*)d_out;

    __nv_bfloat16 *pAh, *pAl, *pWth, *pWtl, *pQh, *pQl, *pKh, *pKl, *pVh, *pVl;
    cudaGetSymbolAddress((void**)&pAh,  g_Ah);
    cudaGetSymbolAddress((void**)&pAl,  g_Al);
    cudaGetSymbolAddress((void**)&pWth, g_Wth);
    cudaGetSymbolAddress((void**)&pWtl, g_Wtl);
    cudaGetSymbolAddress((void**)&pQh,  g_Qh);
    cudaGetSymbolAddress((void**)&pQl,  g_Ql);
    cudaGetSymbolAddress((void**)&pKh,  g_Kh);
    cudaGetSymbolAddress((void**)&pKl,  g_Kl);
    cudaGetSymbolAddress((void**)&pVh,  g_Vth);
    cudaGetSymbolAddress((void**)&pVl,  g_Vtl);

    cudaFuncSetAttribute(gemm_mma_kernel, cudaFuncAttributeMaxDynamicSharedMemorySize, GSMEM_SZ);
    cudaFuncSetAttribute(attn_mma_kernel, cudaFuncAttributeMaxDynamicSharedMemorySize, ASMEM);

    const int n4 = MROWS*DMOD/4;
    const size_t AD = (size_t)MROWS*DMOD;

    wsplit_all<<<dim3(DMOD/32, DMOD/32, 4), dim3(32, 8)>>>(Wq, Wk, Wv, Wo, pWth, pWtl);
    asplit_all<<<dim3(n4/256, 1, 3), 256>>>((const float4*)queries, (const float4*)keys,
                                            (const float4*)values, (uint2*)pAh, (uint2*)pAl, n4);

    // Q alpha folds 1/sqrt(dh) AND log2e so softmax runs in exp2 domain.
    GemmBatch qkv;
    qkv.j[0] = { pAh,        pAl,        pWth,        pWtl,        nullptr, pQh, pQl, 1, 0.18033688f };
    qkv.j[1] = { pAh + AD,   pAl + AD,   pWth + DD,   pWtl + DD,   nullptr, pKh, pKl, 1, 1.0f };
    qkv.j[2] = { pAh + 2*AD, pAl + 2*AD, pWth + 2*DD, pWtl + 2*DD, nullptr, pVh, pVl, 2, 1.0f };
    gemm_mma_kernel<<<dim3(DMOD/64, MROWS/128, 3), 128, GSMEM_SZ>>>(qkv);

    attn_mma_kernel<<<dim3(BSZ*NH, NSEQ/64), 128, ASMEM>>>(pQh, pQl, pKh, pKl, pVh, pVl,
                                                           vlen, pAh, pAl);

    GemmBatch ob;
    ob.j[0] = { pAh, pAl, pWth + 3*DD, pWtl + 3*DD, out, nullptr, nullptr, 0, 1.0f };
    ob.j[1] = ob.j[0]; ob.j[2] = ob.j[0];
    gemm_mma_kernel<<<dim3(DMOD/64, MROWS/128, 1), 128, GSMEM_SZ>>>(ob);
}

// round 9
// speedup vs baseline: 2.8629x; 1.0045x over previous
#include <cuda_runtime.h>
#include <cuda_bf16.h>
#include <cstdint>

#define BSZ   2
#define NSEQ  2048
#define DMOD  1024
#define NH    16
#define DHD   64
#define MROWS (BSZ*NSEQ)
#define DD    (DMOD*DMOD)

// ---------------- device scratch (no allocations allowed) ----------------
__device__ __nv_bfloat16 g_Ah[3*MROWS*DMOD];
__device__ __nv_bfloat16 g_Al[3*MROWS*DMOD];
__device__ __nv_bfloat16 g_Wth[4*DD];
__device__ __nv_bfloat16 g_Wtl[4*DD];
__device__ __nv_bfloat16 g_Qh[MROWS*DMOD];     // [bh][n][dh], pre-scaled by 0.125*log2e
__device__ __nv_bfloat16 g_Ql[MROWS*DMOD];
__device__ __nv_bfloat16 g_Kh[MROWS*DMOD];     // [bh][n][dh]
__device__ __nv_bfloat16 g_Kl[MROWS*DMOD];
__device__ __nv_bfloat16 g_Vth[MROWS*DMOD];    // [bh][dh][n]
__device__ __nv_bfloat16 g_Vtl[MROWS*DMOD];

// ---------------- PTX helpers ----------------
__device__ __forceinline__ uint32_t smem_to_u32(const void* p) {
    uint32_t a;
    asm("{ .reg .u64 t; cvta.to.shared.u64 t, %1; cvt.u32.u64 %0, t; }" : "=r"(a) : "l"(p));
    return a;
}
__device__ __forceinline__ void cp_async16(uint32_t dst, const void* src) {
    asm volatile("cp.async.cg.shared.global [%0], [%1], 16;" :: "r"(dst), "l"(src));
}
__device__ __forceinline__ void cp_commit() {
    asm volatile("cp.async.commit_group;" ::: "memory");
}
template <int N>
__device__ __forceinline__ void cp_wait() {
    asm volatile("cp.async.wait_group %0;" :: "n"(N) : "memory");
}
__device__ __forceinline__ void ldsm_x4(uint32_t& r0, uint32_t& r1, uint32_t& r2,
                                        uint32_t& r3, uint32_t addr) {
    asm volatile("ldmatrix.sync.aligned.m8n8.x4.shared.b16 {%0,%1,%2,%3}, [%4];"
                 : "=r"(r0), "=r"(r1), "=r"(r2), "=r"(r3) : "r"(addr));
}
__device__ __forceinline__ void mma16816(float* c, uint32_t a0, uint32_t a1,
                                         uint32_t a2, uint32_t a3,
                                         uint32_t b0, uint32_t b1) {
    asm volatile("mma.sync.aligned.m16n8k16.row.col.f32.bf16.bf16.f32 "
                 "{%0,%1,%2,%3}, {%4,%5,%6,%7}, {%8,%9}, {%0,%1,%2,%3};"
                 : "+f"(c[0]), "+f"(c[1]), "+f"(c[2]), "+f"(c[3])
                 : "r"(a0), "r"(a1), "r"(a2), "r"(a3), "r"(b0), "r"(b1));
}

// exp2(x) for x <= 0 (inputs already in log2 domain), ~2e-6 rel err.
__device__ __forceinline__ float fexp2(float t) {
    t = fmaxf(t, -126.0f);
    float n = rintf(t);
    float f = t - n;
    float p = 1.3333558e-3f;
    p = fmaf(p, f, 9.6181291e-3f);
    p = fmaf(p, f, 5.5504109e-2f);
    p = fmaf(p, f, 2.4022651e-1f);
    p = fmaf(p, f, 6.9314718e-1f);
    p = fmaf(p, f, 1.0f);
    int e = (int)n;
    return p * __int_as_float((e + 127) << 23);
}

__device__ __forceinline__ uint32_t pack2(float a, float b) {
    uint32_t r;
    asm("cvt.rn.bf16x2.f32 %0, %1, %2;" : "=r"(r) : "f"(b), "f"(a));
    return r;
}
__device__ __forceinline__ uint32_t res_pack(uint32_t hpk, float a, float b) {
    float ha = __int_as_float(hpk << 16);
    float hb = __int_as_float(hpk & 0xffff0000u);
    return pack2(a - ha, b - hb);
}
__device__ __forceinline__ float bf16_res(float x) {
    return x - __bfloat162float(__float2bfloat16(x));
}
#define SWZ(o) ((o) ^ (((o) >> 3) & 0x70))

// ---------------- prep kernels ----------------
__global__ __launch_bounds__(256)
void asplit_all(const float4* __restrict__ X0, const float4* __restrict__ X1,
                const float4* __restrict__ X2, uint2* __restrict__ Xh,
                uint2* __restrict__ Xl, int n4)
{
    const int z = blockIdx.z;
    const float4* X = (z == 0) ? X0 : ((z == 1) ? X1 : X2);
    int i = blockIdx.x*256 + threadIdx.x;
    if (i >= n4) return;
    float4 v = X[i];
    uint2 uh, ul;
    uh.x = pack2(v.x, v.y); uh.y = pack2(v.z, v.w);
    ul.x = res_pack(uh.x, v.x, v.y); ul.y = res_pack(uh.y, v.z, v.w);
    Xh[(size_t)z*n4 + i] = uh; Xl[(size_t)z*n4 + i] = ul;
}

__global__ __launch_bounds__(256)
void wsplit_all(const float* __restrict__ W0, const float* __restrict__ W1,
                const float* __restrict__ W2, const float* __restrict__ W3,
                __nv_bfloat16* __restrict__ Wth, __nv_bfloat16* __restrict__ Wtl)
{
    __shared__ float ts[32][33];
    const int z = blockIdx.z;
    const float* W = (z == 0) ? W0 : ((z == 1) ? W1 : ((z == 2) ? W2 : W3));
    __nv_bfloat16* th = Wth + (size_t)z*DD;
    __nv_bfloat16* tl = Wtl + (size_t)z*DD;
    const int tx = threadIdx.x, ty = threadIdx.y;
    const int gx = blockIdx.x*32, gy = blockIdx.y*32;
    #pragma unroll
    for (int i = ty; i < 32; i += 8)
        ts[i][tx] = W[(size_t)(gy+i)*DMOD + gx + tx];
    __syncthreads();
    #pragma unroll
    for (int i = ty; i < 32; i += 8) {
        float v = ts[tx][i];
        __nv_bfloat16 h = __float2bfloat16(v);
        th[(size_t)(gx+i)*DMOD + gy + tx] = h;
        tl[(size_t)(gx+i)*DMOD + gy + tx] = __float2bfloat16(v - __bfloat162float(h));
    }
}

// ---------------- mma.sync bf16-split GEMM ----------------
// CTA 128(m) x 128(n), 4 warps of 64x64 (2x2), 2 CTAs/SM.
// Per chunk/warp: 192 HMMA on 32 ldsm (6:1) -> tensor pipe is binding resource.
#define KC       32
#define NCHUNK   (DMOD/KC)
#define ROWB     80
#define T_TB     (128*ROWB)          // 10240 per tile (128 rows x 32 bf16)
#define STAGE_B  (4*T_TB)            // Ah, Al, Bh, Bl = 40960
#define GSMEM_SZ (2*STAGE_B)         // 81920

struct GemmJob {
    const __nv_bfloat16 *Ah, *Al, *Bh, *Bl;
    float* C32;
    __nv_bfloat16 *Ch, *Cl;
    int mode;
    float alpha;
};
struct GemmBatch { GemmJob j[3]; };

__device__ __forceinline__ void issue_chunk(uint32_t sb, int stage,
    const __nv_bfloat16* __restrict__ Ah, const __nv_bfloat16* __restrict__ Al,
    const __nv_bfloat16* __restrict__ Bh, const __nv_bfloat16* __restrict__ Bl,
    int m0, int n0, int k0, int tid)
{
    const uint32_t so = sb + stage*STAGE_B;
    const __nv_bfloat16* srcs[4] = {Ah + (size_t)m0*DMOD + k0, Al + (size_t)m0*DMOD + k0,
                                    Bh + (size_t)n0*DMOD + k0, Bl + (size_t)n0*DMOD + k0};
    #pragma unroll
    for (int t = 0; t < 4; t++) {
        #pragma unroll
        for (int i = 0; i < 4; i++) {
            int idx = i*128 + tid;          // 0..511
            int row = idx >> 2, cg = idx & 3;
            cp_async16(so + t*T_TB + row*ROWB + cg*16, srcs[t] + (size_t)row*DMOD + cg*8);
        }
    }
}

__global__ __launch_bounds__(128, 2)
void gemm_mma_kernel(GemmBatch P)
{
    extern __shared__ char smem[];
    const uint32_t sb = smem_to_u32(smem);
    const int tid = threadIdx.x;
    const int wid = tid >> 5, lane = tid & 31;
    const int n0 = blockIdx.x * 128;
    const int m0 = blockIdx.y * 128;
    const GemmJob& J = P.j[blockIdx.z];
    const __nv_bfloat16 *Ah = J.Ah, *Al = J.Al, *Bh = J.Bh, *Bl = J.Bl;

    const int wm = (wid & 1) * 64;
    const int wn = (wid >> 1) * 64;

    const int a_row = lane & 15;
    const int a_kh  = lane >> 4;
    const int b_row = ((lane >> 4) << 3) + (lane & 7);
    const int b_kh  = (lane >> 3) & 1;

    float acc[4][8][4];
    #pragma unroll
    for (int mi = 0; mi < 4; mi++)
      #pragma unroll
      for (int ni = 0; ni < 8; ni++)
        #pragma unroll
        for (int r = 0; r < 4; r++) acc[mi][ni][r] = 0.f;

    issue_chunk(sb, 0, Ah, Al, Bh, Bl, m0, n0, 0, tid);
    cp_commit();

    for (int c = 0; c < NCHUNK; c++) {
        if (c + 1 < NCHUNK) {
            issue_chunk(sb, (c+1) & 1, Ah, Al, Bh, Bl, m0, n0, (c+1)*KC, tid);
            cp_commit();
            cp_wait<1>();
        } else {
            cp_wait<0>();
        }
        __syncthreads();

        const uint32_t so = sb + (c & 1)*STAGE_B;
        #pragma unroll
        for (int ks = 0; ks < 2; ks++) {
            const uint32_t koff = (ks*16 + b_kh*8) * 2;
            uint32_t bh[4][4], bl[4][4];
            #pragma unroll
            for (int np = 0; np < 4; np++) {
                uint32_t ba = so + 2*T_TB + (wn + np*16 + b_row)*ROWB + koff;
                ldsm_x4(bh[np][0], bh[np][1], bh[np][2], bh[np][3], ba);
                ldsm_x4(bl[np][0], bl[np][1], bl[np][2], bl[np][3], ba + T_TB);
            }
            const uint32_t akoff = (ks*16 + a_kh*8) * 2;
            #pragma unroll
            for (int mi = 0; mi < 4; mi++) {
                uint32_t aa = so + (wm + mi*16 + a_row)*ROWB + akoff;
                uint32_t ah0, ah1, ah2, ah3, al0, al1, al2, al3;
                ldsm_x4(ah0, ah1, ah2, ah3, aa);
                ldsm_x4(al0, al1, al2, al3, aa + T_TB);
                #pragma unroll
                for (int ni = 0; ni < 8; ni++) {
                    const int np = ni >> 1, hf = (ni & 1) * 2;
                    mma16816(acc[mi][ni], ah0, ah1, ah2, ah3, bh[np][hf], bh[np][hf+1]);
                    mma16816(acc[mi][ni], ah0, ah1, ah2, ah3, bl[np][hf], bl[np][hf+1]);
                    mma16816(acc[mi][ni], al0, al1, al2, al3, bh[np][hf], bh[np][hf+1]);
                }
            }
        }
        __syncthreads();
    }

    const int crow = lane >> 2, ccol = (lane & 3) * 2;
    const int mode = J.mode;
    const float alpha = J.alpha;
    #pragma unroll
    for (int mi = 0; mi < 4; mi++) {
      #pragma unroll
      for (int h = 0; h < 2; h++) {
        const int m = m0 + wm + mi*16 + crow + h*8;
        const int bb = m >> 11, nn = m & (NSEQ-1);
        #pragma unroll
        for (int ni = 0; ni < 8; ni++) {
            const int n = n0 + wn + ni*8 + ccol;
            float x0 = acc[mi][ni][h*2+0] * alpha;
            float x1 = acc[mi][ni][h*2+1] * alpha;
            if (mode == 0) {
                float2 v; v.x = x0; v.y = x1;
                *(float2*)(&J.C32[(size_t)m*DMOD + n]) = v;
            } else if (mode == 1) {
                const int hh = n >> 6, dh = n & 63;
                size_t base = (((size_t)(bb*NH + hh))*NSEQ + nn)*DHD + dh;
                uint32_t hp = pack2(x0, x1);
                *(uint32_t*)(J.Ch + base) = hp;
                *(uint32_t*)(J.Cl + base) = res_pack(hp, x0, x1);
            } else {
                const int hh = n >> 6, dh = n & 63;
                size_t base = (((size_t)(bb*NH + hh))*DHD + dh)*NSEQ + nn;
                J.Ch[base]        = __float2bfloat16(x0);
                J.Ch[base + NSEQ] = __float2bfloat16(x1);
                J.Cl[base]        = __float2bfloat16(bf16_res(x0));
                J.Cl[base + NSEQ] = __float2bfloat16(bf16_res(x1));
            }
        }
      }
    }
}

// ---------------- tensor-core flash attention (unchanged from R8) ----------
#define AKT   64
#define ATILE 8192
#define ASMEM (8*ATILE)

__device__ __forceinline__ void attn_load_kv(uint32_t sb, int stage,
    const __nv_bfloat16* __restrict__ Kh, const __nv_bfloat16* __restrict__ Kl,
    const __nv_bfloat16* __restrict__ Vh, const __nv_bfloat16* __restrict__ Vl,
    int bh, int k0, int tid)
{
    const __nv_bfloat16* srcs[4] = {
        Kh + ((size_t)bh*NSEQ + k0)*DHD,
        Kl + ((size_t)bh*NSEQ + k0)*DHD,
        Vh + ((size_t)bh*DHD)*NSEQ + k0,
        Vl + ((size_t)bh*DHD)*NSEQ + k0 };
    const int rstr[4] = {DHD, DHD, NSEQ, NSEQ};
    const uint32_t base = sb + stage*(4*ATILE);
    #pragma unroll
    for (int i = 0; i < 16; i++) {
        const int arr = i >> 2;
        const int idx = i*128 + tid;
        const int row = (idx >> 3) & 63;
        const int cg  = idx & 7;
        cp_async16(base + arr*ATILE + SWZ(row*128 + cg*16),
                   srcs[arr] + (size_t)row*rstr[arr] + cg*8);
    }
}

__global__ __launch_bounds__(128, 3)
void attn_mma_kernel(const __nv_bfloat16* __restrict__ Qh, const __nv_bfloat16* __restrict__ Ql,
                     const __nv_bfloat16* __restrict__ Kh, const __nv_bfloat16* __restrict__ Kl,
                     const __nv_bfloat16* __restrict__ Vh, const __nv_bfloat16* __restrict__ Vl,
                     const int* __restrict__ vlen,
                     __nv_bfloat16* __restrict__ Oh, __nv_bfloat16* __restrict__ Ol)
{
    extern __shared__ char smem[];
    const uint32_t sb = smem_to_u32(smem);
    const int tid = threadIdx.x, wid = tid >> 5, lane = tid & 31;
    const int bh = blockIdx.x, qt = blockIdx.y;
    const int vl = vlen[bh];
    const int ntiles = (vl + AKT - 1) / AKT;
    const int wq0 = wid * 16;

    const int crow = lane >> 2, ccol = (lane & 3) * 2;
    const int b_row = ((lane >> 4) << 3) + (lane & 7);
    const int b_kh = (lane >> 3) & 1;

    attn_load_kv(sb, 0, Kh, Kl, Vh, Vl, bh, 0, tid);
    cp_commit();

    uint32_t qfh[4][4], qfl[4][4];
    {
        const __nv_bfloat16* qh = Qh + ((size_t)bh*NSEQ + qt*64 + wq0)*DHD;
        const __nv_bfloat16* ql = Ql + ((size_t)bh*NSEQ + qt*64 + wq0)*DHD;
        #pragma unroll
        for (int ks = 0; ks < 4; ks++) {
            const int col = ks*16 + ccol;
            qfh[ks][0] = *(const uint32_t*)(qh + (size_t)crow*DHD + col);
            qfh[ks][1] = *(const uint32_t*)(qh + (size_t)(crow+8)*DHD + col);
            qfh[ks][2] = *(const uint32_t*)(qh + (size_t)crow*DHD + col + 8);
            qfh[ks][3] = *(const uint32_t*)(qh + (size_t)(crow+8)*DHD + col + 8);
            qfl[ks][0] = *(const uint32_t*)(ql + (size_t)crow*DHD + col);
            qfl[ks][1] = *(const uint32_t*)(ql + (size_t)(crow+8)*DHD + col);
            qfl[ks][2] = *(const uint32_t*)(ql + (size_t)crow*DHD + col + 8);
            qfl[ks][3] = *(const uint32_t*)(ql + (size_t)(crow+8)*DHD + col + 8);
        }
    }

    float o[8][4];
    float m_i[2] = {-1e30f, -1e30f}, l_i[2] = {0.f, 0.f};
    #pragma unroll
    for (int nt = 0; nt < 8; nt++)
        #pragma unroll
        for (int r = 0; r < 4; r++) o[nt][r] = 0.f;

    for (int kt = 0; kt < ntiles; kt++) {
        if (kt + 1 < ntiles) {
            attn_load_kv(sb, (kt+1) & 1, Kh, Kl, Vh, Vl, bh, (kt+1)*AKT, tid);
            cp_commit();
            cp_wait<1>();
        } else {
            cp_wait<0>();
        }
        __syncthreads();

        const uint32_t soK = sb + (kt & 1)*(4*ATILE);

        float s[8][4];
        #pragma unroll
        for (int nt = 0; nt < 8; nt++)
            #pragma unroll
            for (int r = 0; r < 4; r++) s[nt][r] = 0.f;

        #pragma unroll
        for (int ks = 0; ks < 4; ks++) {
            const uint32_t koff = ks*32 + b_kh*16;
            #pragma unroll
            for (int np = 0; np < 4; np++) {
                const uint32_t ro = (np*16 + b_row)*128 + koff;
                const uint32_t ka = soK + SWZ(ro);
                uint32_t kfh[4], kfl[4];
                ldsm_x4(kfh[0], kfh[1], kfh[2], kfh[3], ka);
                ldsm_x4(kfl[0], kfl[1], kfl[2], kfl[3], ka + ATILE);
                #pragma unroll
                for (int t = 0; t < 2; t++) {
                    float* sc = s[np*2 + t];
                    mma16816(sc, qfh[ks][0], qfh[ks][1], qfh[ks][2], qfh[ks][3], kfh[t*2], kfh[t*2+1]);
                    mma16816(sc, qfh[ks][0], qfh[ks][1], qfh[ks][2], qfh[ks][3], kfl[t*2], kfl[t*2+1]);
                    mma16816(sc, qfl[ks][0], qfl[ks][1], qfl[ks][2], qfl[ks][3], kfh[t*2], kfh[t*2+1]);
                }
            }
        }

        const int kb = kt * AKT;
        const bool full = (kb + AKT <= vl);
        #pragma unroll
        for (int h = 0; h < 2; h++) {
            if (!full) {
                #pragma unroll
                for (int nt = 0; nt < 8; nt++) {
                    const int c0 = kb + nt*8 + ccol;
                    if (c0     >= vl) s[nt][h*2]   = -1e30f;
                    if (c0 + 1 >= vl) s[nt][h*2+1] = -1e30f;
                }
            }
            float rmax = -1e30f;
            #pragma unroll
            for (int nt = 0; nt < 8; nt++)
                rmax = fmaxf(rmax, fmaxf(s[nt][h*2], s[nt][h*2+1]));
            rmax = fmaxf(rmax, __shfl_xor_sync(0xffffffffu, rmax, 1));
            rmax = fmaxf(rmax, __shfl_xor_sync(0xffffffffu, rmax, 2));
            const float m_new = fmaxf(m_i[h], rmax);
            const float rsc = fexp2(m_i[h] - m_new);
            m_i[h] = m_new;
            float rsum = 0.f;
            #pragma unroll
            for (int nt = 0; nt < 8; nt++) {
                const float p0 = fexp2(s[nt][h*2]   - m_new);
                const float p1 = fexp2(s[nt][h*2+1] - m_new);
                s[nt][h*2]   = p0;
                s[nt][h*2+1] = p1;
                rsum += p0 + p1;
            }
            rsum += __shfl_xor_sync(0xffffffffu, rsum, 1);
            rsum += __shfl_xor_sync(0xffffffffu, rsum, 2);
            l_i[h] = l_i[h]*rsc + rsum;
            #pragma unroll
            for (int nt = 0; nt < 8; nt++) { o[nt][h*2] *= rsc; o[nt][h*2+1] *= rsc; }
        }

        #pragma unroll
        for (int ks = 0; ks < 4; ks++) {
            const int t0 = 2*ks, t1 = 2*ks + 1;
            const uint32_t ph0 = pack2(s[t0][0], s[t0][1]);
            const uint32_t ph1 = pack2(s[t0][2], s[t0][3]);
            const uint32_t ph2 = pack2(s[t1][0], s[t1][1]);
            const uint32_t ph3 = pack2(s[t1][2], s[t1][3]);
            const uint32_t pl0 = res_pack(ph0, s[t0][0], s[t0][1]);
            const uint32_t pl1 = res_pack(ph1, s[t0][2], s[t0][3]);
            const uint32_t pl2 = res_pack(ph2, s[t1][0], s[t1][1]);
            const uint32_t pl3 = res_pack(ph3, s[t1][2], s[t1][3]);
            const uint32_t koff = ks*32 + b_kh*16;
            #pragma unroll
            for (int np = 0; np < 4; np++) {
                const uint32_t ro = (np*16 + b_row)*128 + koff;
                const uint32_t va = soK + 2*ATILE + SWZ(ro);
                uint32_t vfh[4], vfl[4];
                ldsm_x4(vfh[0], vfh[1], vfh[2], vfh[3], va);
                ldsm_x4(vfl[0], vfl[1], vfl[2], vfl[3], va + ATILE);
                #pragma unroll
                for (int t = 0; t < 2; t++) {
                    float* oc = o[np*2 + t];
                    mma16816(oc, ph0, ph1, ph2, ph3, vfh[t*2], vfh[t*2+1]);
                    mma16816(oc, ph0, ph1, ph2, ph3, vfl[t*2], vfl[t*2+1]);
                    mma16816(oc, pl0, pl1, pl2, pl3, vfh[t*2], vfh[t*2+1]);
                }
            }
        }
        __syncthreads();
    }

    const int bb = bh >> 4, hh = bh & 15;
    #pragma unroll
    for (int h = 0; h < 2; h++) {
        const float inv = 1.0f / l_i[h];
        const int ntok = qt*64 + wq0 + crow + h*8;
        const size_t base = ((size_t)(bb*NSEQ) + ntok)*DMOD + hh*64 + ccol;
        #pragma unroll
        for (int nt = 0; nt < 8; nt++) {
            const float x0 = o[nt][h*2]   * inv;
            const float x1 = o[nt][h*2+1] * inv;
            uint32_t hp = pack2(x0, x1);
            *(uint32_t*)(Oh + base + nt*8) = hp;
            *(uint32_t*)(Ol + base + nt*8) = res_pack(hp, x0, x1);
        }
    }
}

// ---------------------------------------------------------------------------
extern "C" void kernel_launch(void* const* d_in, const int* in_sizes, int n_in,
                              void* d_out, int out_size) {
    const float* queries = (const float*)d_in[0];
    const float* keys    = (const float*)d_in[1];
    const float* values  = (const float*)d_in[2];
    const int*   vlen    = (const int*)  d_in[3];
    const float* Wq      = (const float*)d_in[4];
    const float* Wk      = (const float*)d_in[5];
    const float* Wv      = (const float*)d_in[6];
    const float* Wo      = (const float*)d_in[7];
    float* out = (float*)d_out;

    __nv_bfloat16 *pAh, *pAl, *pWth, *pWtl, *pQh, *pQl, *pKh, *pKl, *pVh, *pVl;
    cudaGetSymbolAddress((void**)&pAh,  g_Ah);
    cudaGetSymbolAddress((void**)&pAl,  g_Al);
    cudaGetSymbolAddress((void**)&pWth, g_Wth);
    cudaGetSymbolAddress((void**)&pWtl, g_Wtl);
    cudaGetSymbolAddress((void**)&pQh,  g_Qh);
    cudaGetSymbolAddress((void**)&pQl,  g_Ql);
    cudaGetSymbolAddress((void**)&pKh,  g_Kh);
    cudaGetSymbolAddress((void**)&pKl,  g_Kl);
    cudaGetSymbolAddress((void**)&pVh,  g_Vth);
    cudaGetSymbolAddress((void**)&pVl,  g_Vtl);

    cudaFuncSetAttribute(gemm_mma_kernel, cudaFuncAttributeMaxDynamicSharedMemorySize, GSMEM_SZ);
    cudaFuncSetAttribute(attn_mma_kernel, cudaFuncAttributeMaxDynamicSharedMemorySize, ASMEM);

    const int n4 = MROWS*DMOD/4;
    const size_t AD = (size_t)MROWS*DMOD;

    wsplit_all<<<dim3(DMOD/32, DMOD/32, 4), dim3(32, 8)>>>(Wq, Wk, Wv, Wo, pWth, pWtl);
    asplit_all<<<dim3(n4/256, 1, 3), 256>>>((const float4*)queries, (const float4*)keys,
                                            (const float4*)values, (uint2*)pAh, (uint2*)pAl, n4);

    GemmBatch qkv;
    qkv.j[0] = { pAh,        pAl,        pWth,        pWtl,        nullptr, pQh, pQl, 1, 0.18033688f };
    qkv.j[1] = { pAh + AD,   pAl + AD,   pWth + DD,   pWtl + DD,   nullptr, pKh, pKl, 1, 1.0f };
    qkv.j[2] = { pAh + 2*AD, pAl + 2*AD, pWth + 2*DD, pWtl + 2*DD, nullptr, pVh, pVl, 2, 1.0f };
    gemm_mma_kernel<<<dim3(DMOD/128, MROWS/128, 3), 128, GSMEM_SZ>>>(qkv);

    attn_mma_kernel<<<dim3(BSZ*NH, NSEQ/64), 128, ASMEM>>>(pQh, pQl, pKh, pKl, pVh, pVl,
                                                           vlen, pAh, pAl);

    GemmBatch ob;
    ob.j[0] = { pAh, pAl, pWth + 3*DD, pWtl + 3*DD, out, nullptr, nullptr, 0, 1.0f };
    ob.j[1] = ob.j[0]; ob.j[2] = ob.j[0];
    gemm_mma_kernel<<<dim3(DMOD/128, MROWS/128, 1), 128, GSMEM_SZ>>>(ob);
}

// round 10
// speedup vs baseline: 3.0223x; 1.0557x over previous
#include <cuda_runtime.h>
#include <cuda_bf16.h>
#include <cstdint>

#define BSZ   2
#define NSEQ  2048
#define DMOD  1024
#define NH    16
#define DHD   64
#define MROWS (BSZ*NSEQ)
#define DD    (DMOD*DMOD)

// ---------------- device scratch (no allocations allowed) ----------------
__device__ __nv_bfloat16 g_Ah[3*MROWS*DMOD];
__device__ __nv_bfloat16 g_Al[3*MROWS*DMOD];
__device__ __nv_bfloat16 g_Wth[4*DD];
__device__ __nv_bfloat16 g_Wtl[4*DD];
__device__ __nv_bfloat16 g_Qh[MROWS*DMOD];     // [bh][n][dh], pre-scaled by 0.125*log2e
__device__ __nv_bfloat16 g_Ql[MROWS*DMOD];
__device__ __nv_bfloat16 g_Kh[MROWS*DMOD];     // [bh][n][dh]
__device__ __nv_bfloat16 g_Kl[MROWS*DMOD];
__device__ __nv_bfloat16 g_Vth[MROWS*DMOD];    // [bh][dh][n]
__device__ __nv_bfloat16 g_Vtl[MROWS*DMOD];

// ---------------- PTX helpers ----------------
__device__ __forceinline__ uint32_t smem_to_u32(const void* p) {
    uint32_t a;
    asm("{ .reg .u64 t; cvta.to.shared.u64 t, %1; cvt.u32.u64 %0, t; }" : "=r"(a) : "l"(p));
    return a;
}
__device__ __forceinline__ void cp_async16(uint32_t dst, const void* src) {
    asm volatile("cp.async.cg.shared.global [%0], [%1], 16;" :: "r"(dst), "l"(src));
}
__device__ __forceinline__ void cp_commit() {
    asm volatile("cp.async.commit_group;" ::: "memory");
}
template <int N>
__device__ __forceinline__ void cp_wait() {
    asm volatile("cp.async.wait_group %0;" :: "n"(N) : "memory");
}
__device__ __forceinline__ void ldsm_x4(uint32_t& r0, uint32_t& r1, uint32_t& r2,
                                        uint32_t& r3, uint32_t addr) {
    asm volatile("ldmatrix.sync.aligned.m8n8.x4.shared.b16 {%0,%1,%2,%3}, [%4];"
                 : "=r"(r0), "=r"(r1), "=r"(r2), "=r"(r3) : "r"(addr));
}
__device__ __forceinline__ void mma16816(float* c, uint32_t a0, uint32_t a1,
                                         uint32_t a2, uint32_t a3,
                                         uint32_t b0, uint32_t b1) {
    asm volatile("mma.sync.aligned.m16n8k16.row.col.f32.bf16.bf16.f32 "
                 "{%0,%1,%2,%3}, {%4,%5,%6,%7}, {%8,%9}, {%0,%1,%2,%3};"
                 : "+f"(c[0]), "+f"(c[1]), "+f"(c[2]), "+f"(c[3])
                 : "r"(a0), "r"(a1), "r"(a2), "r"(a3), "r"(b0), "r"(b1));
}

// exp2(x) for x <= 0 (inputs already in log2 domain), ~2e-6 rel err.
__device__ __forceinline__ float fexp2(float t) {
    t = fmaxf(t, -126.0f);
    float n = rintf(t);
    float f = t - n;
    float p = 1.3333558e-3f;
    p = fmaf(p, f, 9.6181291e-3f);
    p = fmaf(p, f, 5.5504109e-2f);
    p = fmaf(p, f, 2.4022651e-1f);
    p = fmaf(p, f, 6.9314718e-1f);
    p = fmaf(p, f, 1.0f);
    int e = (int)n;
    return p * __int_as_float((e + 127) << 23);
}

__device__ __forceinline__ uint32_t pack2(float a, float b) {
    uint32_t r;
    asm("cvt.rn.bf16x2.f32 %0, %1, %2;" : "=r"(r) : "f"(b), "f"(a));
    return r;
}
__device__ __forceinline__ uint32_t res_pack(uint32_t hpk, float a, float b) {
    float ha = __int_as_float(hpk << 16);
    float hb = __int_as_float(hpk & 0xffff0000u);
    return pack2(a - ha, b - hb);
}
__device__ __forceinline__ float bf16_res(float x) {
    return x - __bfloat162float(__float2bfloat16(x));
}
#define SWZ(o) ((o) ^ (((o) >> 3) & 0x70))

// ---------------- prep kernels ----------------
__global__ __launch_bounds__(256)
void asplit_all(const float4* __restrict__ X0, const float4* __restrict__ X1,
                const float4* __restrict__ X2, uint2* __restrict__ Xh,
                uint2* __restrict__ Xl, int n4)
{
    const int z = blockIdx.z;
    const float4* X = (z == 0) ? X0 : ((z == 1) ? X1 : X2);
    int i = blockIdx.x*256 + threadIdx.x;
    if (i >= n4) return;
    float4 v = X[i];
    uint2 uh, ul;
    uh.x = pack2(v.x, v.y); uh.y = pack2(v.z, v.w);
    ul.x = res_pack(uh.x, v.x, v.y); ul.y = res_pack(uh.y, v.z, v.w);
    Xh[(size_t)z*n4 + i] = uh; Xl[(size_t)z*n4 + i] = ul;
}

__global__ __launch_bounds__(256)
void wsplit_all(const float* __restrict__ W0, const float* __restrict__ W1,
                const float* __restrict__ W2, const float* __restrict__ W3,
                __nv_bfloat16* __restrict__ Wth, __nv_bfloat16* __restrict__ Wtl)
{
    __shared__ float ts[32][33];
    const int z = blockIdx.z;
    const float* W = (z == 0) ? W0 : ((z == 1) ? W1 : ((z == 2) ? W2 : W3));
    __nv_bfloat16* th = Wth + (size_t)z*DD;
    __nv_bfloat16* tl = Wtl + (size_t)z*DD;
    const int tx = threadIdx.x, ty = threadIdx.y;
    const int gx = blockIdx.x*32, gy = blockIdx.y*32;
    #pragma unroll
    for (int i = ty; i < 32; i += 8)
        ts[i][tx] = W[(size_t)(gy+i)*DMOD + gx + tx];
    __syncthreads();
    #pragma unroll
    for (int i = ty; i < 32; i += 8) {
        float v = ts[tx][i];
        __nv_bfloat16 h = __float2bfloat16(v);
        th[(size_t)(gx+i)*DMOD + gy + tx] = h;
        tl[(size_t)(gx+i)*DMOD + gy + tx] = __float2bfloat16(v - __bfloat162float(h));
    }
}

// ---------------- mma.sync bf16-split GEMM ----------------
// CTA 128x128, 4 warps of 64x64, 4-stage cp.async pipeline (KC=16), 2 CTAs/SM.
// 48B row stride: ldsm 16B-chunk bank starts {0,12,24,4,16,28,8,20} words — conflict-free.
#define KC       16
#define NCHUNK   (DMOD/KC)           // 64
#define ROWB     48
#define T_TB     (128*ROWB)          // 6144
#define STAGE_B  (4*T_TB)            // 24576: Ah, Al, Bh, Bl
#define NSTG     4
#define GSMEM_SZ (NSTG*STAGE_B)      // 98304

struct GemmJob {
    const __nv_bfloat16 *Ah, *Al, *Bh, *Bl;
    float* C32;
    __nv_bfloat16 *Ch, *Cl;
    int mode;
    float alpha;
};
struct GemmBatch { GemmJob j[3]; };

__device__ __forceinline__ void issue_chunk(uint32_t sb, int stage,
    const __nv_bfloat16* __restrict__ Ah, const __nv_bfloat16* __restrict__ Al,
    const __nv_bfloat16* __restrict__ Bh, const __nv_bfloat16* __restrict__ Bl,
    int m0, int n0, int k0, int tid)
{
    const uint32_t so = sb + stage*STAGE_B;
    const __nv_bfloat16* srcs[4] = {Ah + (size_t)m0*DMOD + k0, Al + (size_t)m0*DMOD + k0,
                                    Bh + (size_t)n0*DMOD + k0, Bl + (size_t)n0*DMOD + k0};
    #pragma unroll
    for (int t = 0; t < 4; t++) {
        #pragma unroll
        for (int i = 0; i < 2; i++) {
            int idx = i*128 + tid;          // 0..255
            int row = idx >> 1, cg = idx & 1;
            cp_async16(so + t*T_TB + row*ROWB + cg*16, srcs[t] + (size_t)row*DMOD + cg*8);
        }
    }
}

__global__ __launch_bounds__(128, 2)
void gemm_mma_kernel(GemmBatch P)
{
    extern __shared__ char smem[];
    const uint32_t sb = smem_to_u32(smem);
    const int tid = threadIdx.x;
    const int wid = tid >> 5, lane = tid & 31;
    const int n0 = blockIdx.x * 128;
    const int m0 = blockIdx.y * 128;
    const GemmJob& J = P.j[blockIdx.z];
    const __nv_bfloat16 *Ah = J.Ah, *Al = J.Al, *Bh = J.Bh, *Bl = J.Bl;

    const int wm = (wid & 1) * 64;
    const int wn = (wid >> 1) * 64;

    const int a_row = lane & 15;
    const int a_kh  = lane >> 4;
    const int b_row = ((lane >> 4) << 3) + (lane & 7);
    const int b_kh  = (lane >> 3) & 1;

    float acc[4][8][4];
    #pragma unroll
    for (int mi = 0; mi < 4; mi++)
      #pragma unroll
      for (int ni = 0; ni < 8; ni++)
        #pragma unroll
        for (int r = 0; r < 4; r++) acc[mi][ni][r] = 0.f;

    issue_chunk(sb, 0, Ah, Al, Bh, Bl, m0, n0, 0,     tid); cp_commit();
    issue_chunk(sb, 1, Ah, Al, Bh, Bl, m0, n0, KC,    tid); cp_commit();
    issue_chunk(sb, 2, Ah, Al, Bh, Bl, m0, n0, 2*KC,  tid); cp_commit();

    for (int c = 0; c < NCHUNK; c++) {
        cp_wait<2>();                 // stage c landed two commits ago
        __syncthreads();              // readers of stage (c+3)&NSTG-1 (iter c-1) done
        if (c + 3 < NCHUNK)
            issue_chunk(sb, (c+3) & (NSTG-1), Ah, Al, Bh, Bl, m0, n0, (c+3)*KC, tid);
        cp_commit();                  // unconditional: keeps group indexing exact

        const uint32_t so = sb + (c & (NSTG-1))*STAGE_B;
        const uint32_t koff = b_kh*16;
        uint32_t bh[4][4], bl[4][4];
        #pragma unroll
        for (int np = 0; np < 4; np++) {
            uint32_t ba = so + 2*T_TB + (wn + np*16 + b_row)*ROWB + koff;
            ldsm_x4(bh[np][0], bh[np][1], bh[np][2], bh[np][3], ba);
            ldsm_x4(bl[np][0], bl[np][1], bl[np][2], bl[np][3], ba + T_TB);
        }
        const uint32_t akoff = a_kh*16;
        #pragma unroll
        for (int mi = 0; mi < 4; mi++) {
            uint32_t aa = so + (wm + mi*16 + a_row)*ROWB + akoff;
            uint32_t ah0, ah1, ah2, ah3, al0, al1, al2, al3;
            ldsm_x4(ah0, ah1, ah2, ah3, aa);
            ldsm_x4(al0, al1, al2, al3, aa + T_TB);
            #pragma unroll
            for (int ni = 0; ni < 8; ni++) {
                const int np = ni >> 1, hf = (ni & 1) * 2;
                mma16816(acc[mi][ni], ah0, ah1, ah2, ah3, bh[np][hf], bh[np][hf+1]);
                mma16816(acc[mi][ni], ah0, ah1, ah2, ah3, bl[np][hf], bl[np][hf+1]);
                mma16816(acc[mi][ni], al0, al1, al2, al3, bh[np][hf], bh[np][hf+1]);
            }
        }
    }

    const int crow = lane >> 2, ccol = (lane & 3) * 2;
    const int mode = J.mode;
    const float alpha = J.alpha;
    #pragma unroll
    for (int mi = 0; mi < 4; mi++) {
      #pragma unroll
      for (int h = 0; h < 2; h++) {
        const int m = m0 + wm + mi*16 + crow + h*8;
        const int bb = m >> 11, nn = m & (NSEQ-1);
        #pragma unroll
        for (int ni = 0; ni < 8; ni++) {
            const int n = n0 + wn + ni*8 + ccol;
            float x0 = acc[mi][ni][h*2+0] * alpha;
            float x1 = acc[mi][ni][h*2+1] * alpha;
            if (mode == 0) {
                float2 v; v.x = x0; v.y = x1;
                *(float2*)(&J.C32[(size_t)m*DMOD + n]) = v;
            } else if (mode == 1) {
                const int hh = n >> 6, dh = n & 63;
                size_t base = (((size_t)(bb*NH + hh))*NSEQ + nn)*DHD + dh;
                uint32_t hp = pack2(x0, x1);
                *(uint32_t*)(J.Ch + base) = hp;
                *(uint32_t*)(J.Cl + base) = res_pack(hp, x0, x1);
            } else {
                const int hh = n >> 6, dh = n & 63;
                size_t base = (((size_t)(bb*NH + hh))*DHD + dh)*NSEQ + nn;
                J.Ch[base]        = __float2bfloat16(x0);
                J.Ch[base + NSEQ] = __float2bfloat16(x1);
                J.Cl[base]        = __float2bfloat16(bf16_res(x0));
                J.Cl[base + NSEQ] = __float2bfloat16(bf16_res(x1));
            }
        }
      }
    }
}

// ---------------- tensor-core flash attention (single sync per k-tile) -----
#define AKT   64
#define ATILE 8192
#define ASMEM (8*ATILE)

__device__ __forceinline__ void attn_load_kv(uint32_t sb, int stage,
    const __nv_bfloat16* __restrict__ Kh, const __nv_bfloat16* __restrict__ Kl,
    const __nv_bfloat16* __restrict__ Vh, const __nv_bfloat16* __restrict__ Vl,
    int bh, int k0, int tid)
{
    const __nv_bfloat16* srcs[4] = {
        Kh + ((size_t)bh*NSEQ + k0)*DHD,
        Kl + ((size_t)bh*NSEQ + k0)*DHD,
        Vh + ((size_t)bh*DHD)*NSEQ + k0,
        Vl + ((size_t)bh*DHD)*NSEQ + k0 };
    const int rstr[4] = {DHD, DHD, NSEQ, NSEQ};
    const uint32_t base = sb + stage*(4*ATILE);
    #pragma unroll
    for (int i = 0; i < 16; i++) {
        const int arr = i >> 2;
        const int idx = i*128 + tid;
        const int row = (idx >> 3) & 63;
        const int cg  = idx & 7;
        cp_async16(base + arr*ATILE + SWZ(row*128 + cg*16),
                   srcs[arr] + (size_t)row*rstr[arr] + cg*8);
    }
}

__global__ __launch_bounds__(128, 3)
void attn_mma_kernel(const __nv_bfloat16* __restrict__ Qh, const __nv_bfloat16* __restrict__ Ql,
                     const __nv_bfloat16* __restrict__ Kh, const __nv_bfloat16* __restrict__ Kl,
                     const __nv_bfloat16* __restrict__ Vh, const __nv_bfloat16* __restrict__ Vl,
                     const int* __restrict__ vlen,
                     __nv_bfloat16* __restrict__ Oh, __nv_bfloat16* __restrict__ Ol)
{
    extern __shared__ char smem[];
    const uint32_t sb = smem_to_u32(smem);
    const int tid = threadIdx.x, wid = tid >> 5, lane = tid & 31;
    const int bh = blockIdx.x, qt = blockIdx.y;
    const int vl = vlen[bh];
    const int ntiles = (vl + AKT - 1) / AKT;
    const int wq0 = wid * 16;

    const int crow = lane >> 2, ccol = (lane & 3) * 2;
    const int b_row = ((lane >> 4) << 3) + (lane & 7);
    const int b_kh = (lane >> 3) & 1;

    attn_load_kv(sb, 0, Kh, Kl, Vh, Vl, bh, 0, tid);
    cp_commit();

    uint32_t qfh[4][4], qfl[4][4];
    {
        const __nv_bfloat16* qh = Qh + ((size_t)bh*NSEQ + qt*64 + wq0)*DHD;
        const __nv_bfloat16* ql = Ql + ((size_t)bh*NSEQ + qt*64 + wq0)*DHD;
        #pragma unroll
        for (int ks = 0; ks < 4; ks++) {
            const int col = ks*16 + ccol;
            qfh[ks][0] = *(const uint32_t*)(qh + (size_t)crow*DHD + col);
            qfh[ks][1] = *(const uint32_t*)(qh + (size_t)(crow+8)*DHD + col);
            qfh[ks][2] = *(const uint32_t*)(qh + (size_t)crow*DHD + col + 8);
            qfh[ks][3] = *(const uint32_t*)(qh + (size_t)(crow+8)*DHD + col + 8);
            qfl[ks][0] = *(const uint32_t*)(ql + (size_t)crow*DHD + col);
            qfl[ks][1] = *(const uint32_t*)(ql + (size_t)(crow+8)*DHD + col);
            qfl[ks][2] = *(const uint32_t*)(ql + (size_t)crow*DHD + col + 8);
            qfl[ks][3] = *(const uint32_t*)(ql + (size_t)(crow+8)*DHD + col + 8);
        }
    }

    float o[8][4];
    float m_i[2] = {-1e30f, -1e30f}, l_i[2] = {0.f, 0.f};
    #pragma unroll
    for (int nt = 0; nt < 8; nt++)
        #pragma unroll
        for (int r = 0; r < 4; r++) o[nt][r] = 0.f;

    for (int kt = 0; kt < ntiles; kt++) {
        cp_wait<0>();                 // stage kt data arrived (issued >=1 iter ago)
        __syncthreads();              // readers of stage (kt+1)&1 (iter kt-1) done
        if (kt + 1 < ntiles) {
            attn_load_kv(sb, (kt+1) & 1, Kh, Kl, Vh, Vl, bh, (kt+1)*AKT, tid);
            cp_commit();
        }

        const uint32_t soK = sb + (kt & 1)*(4*ATILE);

        float s[8][4];
        #pragma unroll
        for (int nt = 0; nt < 8; nt++)
            #pragma unroll
            for (int r = 0; r < 4; r++) s[nt][r] = 0.f;

        #pragma unroll
        for (int ks = 0; ks < 4; ks++) {
            const uint32_t koff = ks*32 + b_kh*16;
            #pragma unroll
            for (int np = 0; np < 4; np++) {
                const uint32_t ro = (np*16 + b_row)*128 + koff;
                const uint32_t ka = soK + SWZ(ro);
                uint32_t kfh[4], kfl[4];
                ldsm_x4(kfh[0], kfh[1], kfh[2], kfh[3], ka);
                ldsm_x4(kfl[0], kfl[1], kfl[2], kfl[3], ka + ATILE);
                #pragma unroll
                for (int t = 0; t < 2; t++) {
                    float* sc = s[np*2 + t];
                    mma16816(sc, qfh[ks][0], qfh[ks][1], qfh[ks][2], qfh[ks][3], kfh[t*2], kfh[t*2+1]);
                    mma16816(sc, qfh[ks][0], qfh[ks][1], qfh[ks][2], qfh[ks][3], kfl[t*2], kfl[t*2+1]);
                    mma16816(sc, qfl[ks][0], qfl[ks][1], qfl[ks][2], qfl[ks][3], kfh[t*2], kfh[t*2+1]);
                }
            }
        }

        const int kb = kt * AKT;
        const bool full = (kb + AKT <= vl);
        #pragma unroll
        for (int h = 0; h < 2; h++) {
            if (!full) {
                #pragma unroll
                for (int nt = 0; nt < 8; nt++) {
                    const int c0 = kb + nt*8 + ccol;
                    if (c0     >= vl) s[nt][h*2]   = -1e30f;
                    if (c0 + 1 >= vl) s[nt][h*2+1] = -1e30f;
                }
            }
            float rmax = -1e30f;
            #pragma unroll
            for (int nt = 0; nt < 8; nt++)
                rmax = fmaxf(rmax, fmaxf(s[nt][h*2], s[nt][h*2+1]));
            rmax = fmaxf(rmax, __shfl_xor_sync(0xffffffffu, rmax, 1));
            rmax = fmaxf(rmax, __shfl_xor_sync(0xffffffffu, rmax, 2));
            const float m_new = fmaxf(m_i[h], rmax);
            const float rsc = fexp2(m_i[h] - m_new);
            m_i[h] = m_new;
            float rsum = 0.f;
            #pragma unroll
            for (int nt = 0; nt < 8; nt++) {
                const float p0 = fexp2(s[nt][h*2]   - m_new);
                const float p1 = fexp2(s[nt][h*2+1] - m_new);
                s[nt][h*2]   = p0;
                s[nt][h*2+1] = p1;
                rsum += p0 + p1;
            }
            rsum += __shfl_xor_sync(0xffffffffu, rsum, 1);
            rsum += __shfl_xor_sync(0xffffffffu, rsum, 2);
            l_i[h] = l_i[h]*rsc + rsum;
            #pragma unroll
            for (int nt = 0; nt < 8; nt++) { o[nt][h*2] *= rsc; o[nt][h*2+1] *= rsc; }
        }

        #pragma unroll
        for (int ks = 0; ks < 4; ks++) {
            const int t0 = 2*ks, t1 = 2*ks + 1;
            const uint32_t ph0 = pack2(s[t0][0], s[t0][1]);
            const uint32_t ph1 = pack2(s[t0][2], s[t0][3]);
            const uint32_t ph2 = pack2(s[t1][0], s[t1][1]);
            const uint32_t ph3 = pack2(s[t1][2], s[t1][3]);
            const uint32_t pl0 = res_pack(ph0, s[t0][0], s[t0][1]);
            const uint32_t pl1 = res_pack(ph1, s[t0][2], s[t0][3]);
            const uint32_t pl2 = res_pack(ph2, s[t1][0], s[t1][1]);
            const uint32_t pl3 = res_pack(ph3, s[t1][2], s[t1][3]);
            const uint32_t koff = ks*32 + b_kh*16;
            #pragma unroll
            for (int np = 0; np < 4; np++) {
                const uint32_t ro = (np*16 + b_row)*128 + koff;
                const uint32_t va = soK + 2*ATILE + SWZ(ro);
                uint32_t vfh[4], vfl[4];
                ldsm_x4(vfh[0], vfh[1], vfh[2], vfh[3], va);
                ldsm_x4(vfl[0], vfl[1], vfl[2], vfl[3], va + ATILE);
                #pragma unroll
                for (int t = 0; t < 2; t++) {
                    float* oc = o[np*2 + t];
                    mma16816(oc, ph0, ph1, ph2, ph3, vfh[t*2], vfh[t*2+1]);
                    mma16816(oc, ph0, ph1, ph2, ph3, vfl[t*2], vfl[t*2+1]);
                    mma16816(oc, pl0, pl1, pl2, pl3, vfh[t*2], vfh[t*2+1]);
                }
            }
        }
    }

    const int bb = bh >> 4, hh = bh & 15;
    #pragma unroll
    for (int h = 0; h < 2; h++) {
        const float inv = 1.0f / l_i[h];
        const int ntok = qt*64 + wq0 + crow + h*8;
        const size_t base = ((size_t)(bb*NSEQ) + ntok)*DMOD + hh*64 + ccol;
        #pragma unroll
        for (int nt = 0; nt < 8; nt++) {
            const float x0 = o[nt][h*2]   * inv;
            const float x1 = o[nt][h*2+1] * inv;
            uint32_t hp = pack2(x0, x1);
            *(uint32_t*)(Oh + base + nt*8) = hp;
            *(uint32_t*)(Ol + base + nt*8) = res_pack(hp, x0, x1);
        }
    }
}

// ---------------------------------------------------------------------------
extern "C" void kernel_launch(void* const* d_in, const int* in_sizes, int n_in,
                              void* d_out, int out_size) {
    const float* queries = (const float*)d_in[0];
    const float* keys    = (const float*)d_in[1];
    const float* values  = (const float*)d_in[2];
    const int*   vlen    = (const int*)  d_in[3];
    const float* Wq      = (const float*)d_in[4];
    const float* Wk      = (const float*)d_in[5];
    const float* Wv      = (const float*)d_in[6];
    const float* Wo      = (const float*)d_in[7];
    float* out = (float*)d_out;

    __nv_bfloat16 *pAh, *pAl, *pWth, *pWtl, *pQh, *pQl, *pKh, *pKl, *pVh, *pVl;
    cudaGetSymbolAddress((void**)&pAh,  g_Ah);
    cudaGetSymbolAddress((void**)&pAl,  g_Al);
    cudaGetSymbolAddress((void**)&pWth, g_Wth);
    cudaGetSymbolAddress((void**)&pWtl, g_Wtl);
    cudaGetSymbolAddress((void**)&pQh,  g_Qh);
    cudaGetSymbolAddress((void**)&pQl,  g_Ql);
    cudaGetSymbolAddress((void**)&pKh,  g_Kh);
    cudaGetSymbolAddress((void**)&pKl,  g_Kl);
    cudaGetSymbolAddress((void**)&pVh,  g_Vth);
    cudaGetSymbolAddress((void**)&pVl,  g_Vtl);

    cudaFuncSetAttribute(gemm_mma_kernel, cudaFuncAttributeMaxDynamicSharedMemorySize, GSMEM_SZ);
    cudaFuncSetAttribute(attn_mma_kernel, cudaFuncAttributeMaxDynamicSharedMemorySize, ASMEM);

    const int n4 = MROWS*DMOD/4;
    const size_t AD = (size_t)MROWS*DMOD;

    wsplit_all<<<dim3(DMOD/32, DMOD/32, 4), dim3(32, 8)>>>(Wq, Wk, Wv, Wo, pWth, pWtl);
    asplit_all<<<dim3(n4/256, 1, 3), 256>>>((const float4*)queries, (const float4*)keys,
                                            (const float4*)values, (uint2*)pAh, (uint2*)pAl, n4);

    GemmBatch qkv;
    qkv.j[0] = { pAh,        pAl,        pWth,        pWtl,        nullptr, pQh, pQl, 1, 0.18033688f };
    qkv.j[1] = { pAh + AD,   pAl + AD,   pWth + DD,   pWtl + DD,   nullptr, pKh, pKl, 1, 1.0f };
    qkv.j[2] = { pAh + 2*AD, pAl + 2*AD, pWth + 2*DD, pWtl + 2*DD, nullptr, pVh, pVl, 2, 1.0f };
    gemm_mma_kernel<<<dim3(DMOD/128, MROWS/128, 3), 128, GSMEM_SZ>>>(qkv);

    attn_mma_kernel<<<dim3(BSZ*NH, NSEQ/64), 128, ASMEM>>>(pQh, pQl, pKh, pKl, pVh, pVl,
                                                           vlen, pAh, pAl);

    GemmBatch ob;
    ob.j[0] = { pAh, pAl, pWth + 3*DD, pWtl + 3*DD, out, nullptr, nullptr, 0, 1.0f };
    ob.j[1] = ob.j[0]; ob.j[2] = ob.j[0];
    gemm_mma_kernel<<<dim3(DMOD/128, MROWS/128, 1), 128, GSMEM_SZ>>>(ob);
}